// round 7
// baseline (speedup 1.0000x reference)
#include <cuda_runtime.h>
#include <cuda_fp16.h>
#include <cstdint>

// Problem constants
#define BB 2
#define TT 2048
#define HH 16
#define DD 64
#define CC 1024
#define MM (BB*TT)        // 4096 rows
#define NQKV (3*CC)       // 3072

// Scratch (device globals -- no allocation allowed)
__device__ float  g_qkv[MM * NQKV];        // [4096, 3072] fp32 qkv
__device__ __half g_xh[MM * CC];           // x in fp16
__device__ __half g_wqkvh[NQKV * CC];      // w_qkv in fp16
__device__ __half g_wouth[CC * CC];        // w_out in fp16
__device__ __half g_qh[BB*HH*TT*DD];       // [bh][t][d] fp16
__device__ __half g_kh[BB*HH*TT*DD];       // [bh][t][d] fp16
__device__ __half g_vh[BB*HH*DD*TT];       // [bh][d][t] fp16 (d-major)
__device__ __half g_atth[MM * CC];         // attention out, fp16 [B,T,C]

__device__ __forceinline__ float ex2(float x) {
    float y;
    asm("ex2.approx.ftz.f32 %0, %1;" : "=f"(y) : "f"(x));
    return y;
}

__device__ __forceinline__ void mma_f16(float* d, const uint32_t* a, const uint32_t* b) {
    asm volatile(
        "mma.sync.aligned.m16n8k16.row.col.f32.f16.f16.f32 "
        "{%0,%1,%2,%3},{%4,%5,%6,%7},{%8,%9},{%0,%1,%2,%3};\n"
        : "+f"(d[0]), "+f"(d[1]), "+f"(d[2]), "+f"(d[3])
        : "r"(a[0]), "r"(a[1]), "r"(a[2]), "r"(a[3]), "r"(b[0]), "r"(b[1]));
}

__device__ __forceinline__ void cp16(uint32_t smem_addr, const void* gptr) {
    asm volatile("cp.async.cg.shared.global [%0], [%1], 16;\n"
                 :: "r"(smem_addr), "l"(gptr));
}

// ---------------------------------------------------------------------------
// fp32 -> fp16 convert (vectorized, 8 elems/thread)
// ---------------------------------------------------------------------------
__global__ __launch_bounds__(256) void cvt_h(
    const float* __restrict__ src, __half* __restrict__ dst, int n)
{
    int i = (blockIdx.x * blockDim.x + threadIdx.x) * 8;
    if (i >= n) return;
    float4 v0 = *(const float4*)(src + i);
    float4 v1 = *(const float4*)(src + i + 4);
    __half2 h0 = __floats2half2_rn(v0.x, v0.y);
    __half2 h1 = __floats2half2_rn(v0.z, v0.w);
    __half2 h2 = __floats2half2_rn(v1.x, v1.y);
    __half2 h3 = __floats2half2_rn(v1.z, v1.w);
    uint4 o;
    o.x = *(uint32_t*)&h0; o.y = *(uint32_t*)&h1;
    o.z = *(uint32_t*)&h2; o.w = *(uint32_t*)&h3;
    *(uint4*)(dst + i) = o;
}

// ---------------------------------------------------------------------------
// fp16 tensor-core GEMM: C[m][n] = sum_k A[m][k] * B[n][k]  (fp32 out)
// BM=128 BN=128 BK=32, 256 thr (8 warps, 64x32 each), 3-stage cp.async.
// smem rows padded to 40 halves (80B): frag banks (20*gm+gk)%32 bijection,
// cp.async phases 20*drow%32 distinct -> conflict-free.
// ---------------------------------------------------------------------------
#define HBK 32
#define HPITCH 40                         // halves per padded row
#define HTILE_B (128*HPITCH*2)            // 10240 bytes per matrix tile
#define HSTAGE_B (2*HTILE_B)              // 20480
#define GEMMH_SMEM_BYTES (3*HSTAGE_B)     // 61440

__global__ __launch_bounds__(256, 2) void gemm_f16(
    const __half* __restrict__ A, const __half* __restrict__ Bm,
    float* __restrict__ C, int M, int N, int K)
{
    extern __shared__ char smc[];
    uint32_t smem_u32 = (uint32_t)__cvta_generic_to_shared(smc);

    const int tid  = threadIdx.x;
    const int lane = tid & 31;
    const int warp = tid >> 5;
    const int wm = warp & 1;              // 0..1 : 64 rows
    const int wn = warp >> 1;             // 0..3 : 32 cols
    const int m0 = blockIdx.y * 128;
    const int n0 = blockIdx.x * 128;
    const int gm = lane >> 2;
    const int gk = lane & 3;

    // loader: thread -> row = tid&127, gsel = tid>>7; granules {gsel, gsel+2}
    const int lrow = tid & 127;
    const int gsel = tid >> 7;
    const __half* Ag = A  + (size_t)(m0 + lrow) * K + gsel * 8;
    const __half* Bg = Bm + (size_t)(n0 + lrow) * K + gsel * 8;
    const uint32_t srow = (uint32_t)(lrow * 80 + gsel * 16);

    float acc[16][4];
    #pragma unroll
    for (int t = 0; t < 16; t++)
        #pragma unroll
        for (int r = 0; r < 4; r++) acc[t][r] = 0.f;

    const int NI = K / HBK;

    auto issue = [&](int s, int kt) {
        uint32_t ab = smem_u32 + s * HSTAGE_B + srow;
        uint32_t bb = ab + HTILE_B;
        const __half* asrc = Ag + kt * HBK;
        const __half* bsrc = Bg + kt * HBK;
        cp16(ab,      asrc);
        cp16(ab + 32, asrc + 16);
        cp16(bb,      bsrc);
        cp16(bb + 32, bsrc + 16);
    };

    issue(0, 0);
    asm volatile("cp.async.commit_group;\n");
    if (NI > 1) issue(1, 1);
    asm volatile("cp.async.commit_group;\n");

    for (int it = 0; it < NI; it++) {
        __syncthreads();
        if (it + 2 < NI) issue((it + 2) % 3, it + 2);
        asm volatile("cp.async.commit_group;\n");
        asm volatile("cp.async.wait_group 2;\n");
        __syncthreads();

        const char* As = smc + (it % 3) * HSTAGE_B;
        const char* Bs = As + HTILE_B;

        #pragma unroll
        for (int s = 0; s < 2; s++) {      // k-steps of 16
            uint32_t a4[4][4];
            #pragma unroll
            for (int i = 0; i < 4; i++) {
                const char* ar = As + (wm * 64 + 16 * i + gm) * 80 + s * 32 + gk * 4;
                a4[i][0] = *(const uint32_t*)(ar);
                a4[i][1] = *(const uint32_t*)(ar + 8 * 80);
                a4[i][2] = *(const uint32_t*)(ar + 16);
                a4[i][3] = *(const uint32_t*)(ar + 8 * 80 + 16);
            }
            uint32_t b4[4][2];
            #pragma unroll
            for (int j = 0; j < 4; j++) {
                const char* br = Bs + (wn * 32 + 8 * j + gm) * 80 + s * 32 + gk * 4;
                b4[j][0] = *(const uint32_t*)(br);
                b4[j][1] = *(const uint32_t*)(br + 16);
            }
            #pragma unroll
            for (int i = 0; i < 4; i++)
                #pragma unroll
                for (int j = 0; j < 4; j++)
                    mma_f16(acc[i * 4 + j], a4[i], b4[j]);
        }
    }

    #pragma unroll
    for (int i = 0; i < 4; i++) {
        #pragma unroll
        for (int j = 0; j < 4; j++) {
            float* a = acc[i * 4 + j];
            int r = m0 + wm * 64 + 16 * i + gm;
            int c = n0 + wn * 32 + 8 * j + (gk << 1);
            float2 v0 = {a[0], a[1]};
            float2 v1 = {a[2], a[3]};
            *(float2*)(C + (size_t)r * N + c) = v0;
            *(float2*)(C + (size_t)(r + 8) * N + c) = v1;
        }
    }
}

// ---------------------------------------------------------------------------
// RoPE + scatter q,k -> fp16 [bh][t][d]. (V handled by v_transpose.)
// ---------------------------------------------------------------------------
__global__ __launch_bounds__(256) void rope_scatter(
    const float* __restrict__ cosp, const float* __restrict__ sinp)
{
    int idx = blockIdx.x * blockDim.x + threadIdx.x;
    if (idx >= BB * TT * HH * 32) return;
    int d = idx & 31;
    int h = (idx >> 5) & (HH - 1);
    int t = (idx >> 9) & (TT - 1);
    int b = idx >> 20;

    const float* row = g_qkv + (size_t)(b * TT + t) * NQKV;
    int base = h * DD + d;

    float c0 = cosp[t * DD + d],      c1 = cosp[t * DD + d + 32];
    float s0 = sinp[t * DD + d],      s1 = sinp[t * DD + d + 32];

    float q0 = row[base],            q1 = row[base + 32];
    float k0 = row[CC + base],       k1 = row[CC + base + 32];

    size_t hoff = ((size_t)(b * HH + h) * TT + t) * DD + d;
    g_qh[hoff]      = __float2half(q0 * c0 - q1 * s0);
    g_qh[hoff + 32] = __float2half(q1 * c1 + q0 * s1);
    g_kh[hoff]      = __float2half(k0 * c0 - k1 * s0);
    g_kh[hoff + 32] = __float2half(k1 * c1 + k0 * s1);
}

// ---------------------------------------------------------------------------
// V transpose: g_qkv v-part [b,t,h*64+d] -> g_vh [bh][d][t] fp16.
// ---------------------------------------------------------------------------
__global__ __launch_bounds__(256) void v_transpose()
{
    __shared__ __half s[64][40];

    const int bh = blockIdx.y;
    const int b = bh >> 4, h = bh & 15;
    const int t0 = blockIdx.x * 32;
    const int tid = threadIdx.x;

    {
        int t = tid >> 3;
        int d8 = (tid & 7) << 3;
        const float* src = g_qkv + (size_t)(b * TT + t0 + t) * NQKV + 2 * CC + h * DD + d8;
        float4 v0 = *(const float4*)(src);
        float4 v1 = *(const float4*)(src + 4);
        s[d8 + 0][t] = __float2half(v0.x);
        s[d8 + 1][t] = __float2half(v0.y);
        s[d8 + 2][t] = __float2half(v0.z);
        s[d8 + 3][t] = __float2half(v0.w);
        s[d8 + 4][t] = __float2half(v1.x);
        s[d8 + 5][t] = __float2half(v1.y);
        s[d8 + 6][t] = __float2half(v1.z);
        s[d8 + 7][t] = __float2half(v1.w);
    }
    __syncthreads();

    {
        int d = tid >> 2;
        int tq = (tid & 3) << 3;
        uint4 v = *(const uint4*)&s[d][tq];
        __half* dst = g_vh + ((size_t)bh * DD + d) * TT + t0 + tq;
        *(uint4*)dst = v;
    }
}

// ---------------------------------------------------------------------------
// fp16 tensor-core causal flash attention (epilogue now writes fp16).
// ---------------------------------------------------------------------------
#define KT 64
#define PADH 72
#define KTILE_B (KT*PADH*2)          // 9216 bytes
#define STAGE_B (2*KTILE_B)
#define ATTN_SMEM_BYTES (2*STAGE_B)  // 36864

__global__ __launch_bounds__(256, 2) void attn_mma_h(float kscale)
{
    const int bh = blockIdx.y;
    const int q0 = (gridDim.x - 1 - blockIdx.x) * 128;
    const int b = bh >> 4, h = bh & 15;
    const int tid = threadIdx.x;
    const int lane = tid & 31;
    const int w = tid >> 5;
    const int gm = lane >> 2;
    const int gk = lane & 3;

    const __half* Qp = g_qh + (size_t)bh * TT * DD;
    const __half* Kp = g_kh + (size_t)bh * TT * DD;
    const __half* Vp = g_vh + (size_t)bh * DD * TT;

    extern __shared__ char smc[];
    uint32_t smem_u32 = (uint32_t)__cvta_generic_to_shared(smc);

    const int rowA = q0 + w * 16 + gm;
    const int wrow_lo = q0 + w * 16;
    const int wrow_hi = wrow_lo + 15;

    uint32_t qf[4][4];
    #pragma unroll
    for (int s = 0; s < 4; s++) {
        const __half* r0 = Qp + (size_t)rowA * DD + 16 * s + 2 * gk;
        const __half* r1 = Qp + (size_t)(rowA + 8) * DD + 16 * s + 2 * gk;
        qf[s][0] = *(const uint32_t*)r0;
        qf[s][1] = *(const uint32_t*)r1;
        qf[s][2] = *(const uint32_t*)(r0 + 8);
        qf[s][3] = *(const uint32_t*)(r1 + 8);
    }

    float o[8][4];
    #pragma unroll
    for (int n = 0; n < 8; n++)
        #pragma unroll
        for (int r = 0; r < 4; r++) o[n][r] = 0.f;
    float mA = -1e30f, mB = -1e30f, lA = 0.f, lB = 0.f;

    const int ntiles = (q0 + 128) / KT;

    const int ldrow = tid & 63;
    const int ldc2 = tid >> 6;
    auto issueKV = [&](int jt, int buf) {
        const char* kg = (const char*)(Kp + (size_t)jt * KT * DD);
        const char* vg = (const char*)(Vp + jt * KT);
        uint32_t kb = smem_u32 + buf * STAGE_B;
        uint32_t vb = kb + KTILE_B;
        uint32_t so = (uint32_t)(ldrow * (PADH * 2) + ldc2 * 16);
        cp16(kb + so,      kg + ldrow * 128 + ldc2 * 16);
        cp16(kb + so + 64, kg + ldrow * 128 + ldc2 * 16 + 64);
        cp16(vb + so,      vg + (size_t)ldrow * (TT * 2) + ldc2 * 16);
        cp16(vb + so + 64, vg + (size_t)ldrow * (TT * 2) + ldc2 * 16 + 64);
    };

    issueKV(0, 0);
    asm volatile("cp.async.commit_group;\n");

    for (int jt = 0; jt < ntiles; jt++) {
        if (jt + 1 < ntiles) {
            issueKV(jt + 1, (jt + 1) & 1);
            asm volatile("cp.async.commit_group;\n");
            asm volatile("cp.async.wait_group 1;\n");
        } else {
            asm volatile("cp.async.wait_group 0;\n");
        }
        __syncthreads();

        const char* Ks = smc + (jt & 1) * STAGE_B;
        const char* Vs = Ks + KTILE_B;
        const int j0 = jt * KT;

        #pragma unroll
        for (int c = 0; c < 2; c++) {
            const int c0 = j0 + 32 * c;
            if (c0 > wrow_hi) break;

            float sf[4][4];
            #pragma unroll
            for (int j = 0; j < 4; j++) {
                #pragma unroll
                for (int r = 0; r < 4; r++) sf[j][r] = 0.f;
                const char* kr = Ks + (32 * c + 8 * j + gm) * (PADH * 2) + 4 * gk;
                #pragma unroll
                for (int s = 0; s < 4; s++) {
                    uint32_t bq[2];
                    bq[0] = *(const uint32_t*)(kr + 32 * s);
                    bq[1] = *(const uint32_t*)(kr + 32 * s + 16);
                    mma_f16(sf[j], qf[s], bq);
                }
            }

            const bool needmask = (c0 + 31 > wrow_lo);
            float mxA = -1e30f, mxB = -1e30f;
            #pragma unroll
            for (int j = 0; j < 4; j++) {
                #pragma unroll
                for (int e = 0; e < 2; e++) {
                    int col = c0 + 8 * j + 2 * gk + e;
                    float v0 = sf[j][e] * kscale;
                    float v1 = sf[j][2 + e] * kscale;
                    if (needmask) {
                        if (col > rowA)     v0 = -1e30f;
                        if (col > rowA + 8) v1 = -1e30f;
                    }
                    sf[j][e] = v0; sf[j][2 + e] = v1;
                    mxA = fmaxf(mxA, v0); mxB = fmaxf(mxB, v1);
                }
            }
            mxA = fmaxf(mxA, __shfl_xor_sync(0xffffffffu, mxA, 1));
            mxA = fmaxf(mxA, __shfl_xor_sync(0xffffffffu, mxA, 2));
            mxB = fmaxf(mxB, __shfl_xor_sync(0xffffffffu, mxB, 1));
            mxB = fmaxf(mxB, __shfl_xor_sync(0xffffffffu, mxB, 2));

            float nmA = fmaxf(mA, mxA), nmB = fmaxf(mB, mxB);
            float aA = ex2(mA - nmA), aB = ex2(mB - nmB);
            mA = nmA; mB = nmB;

            #pragma unroll
            for (int n = 0; n < 8; n++) {
                o[n][0] *= aA; o[n][1] *= aA;
                o[n][2] *= aB; o[n][3] *= aB;
            }
            lA *= aA; lB *= aB;

            uint32_t ph[4][2];
            float slA = 0.f, slB = 0.f;
            #pragma unroll
            for (int j = 0; j < 4; j++) {
                float p0 = ex2(sf[j][0] - mA);
                float p1 = ex2(sf[j][1] - mA);
                float p2 = ex2(sf[j][2] - mB);
                float p3 = ex2(sf[j][3] - mB);
                slA += p0 + p1; slB += p2 + p3;
                __half2 h01 = __floats2half2_rn(p0, p1);
                __half2 h23 = __floats2half2_rn(p2, p3);
                ph[j][0] = *(const uint32_t*)&h01;
                ph[j][1] = *(const uint32_t*)&h23;
            }
            slA += __shfl_xor_sync(0xffffffffu, slA, 1);
            slA += __shfl_xor_sync(0xffffffffu, slA, 2);
            slB += __shfl_xor_sync(0xffffffffu, slB, 1);
            slB += __shfl_xor_sync(0xffffffffu, slB, 2);
            lA += slA; lB += slB;

            #pragma unroll
            for (int s2 = 0; s2 < 2; s2++) {
                uint32_t af[4] = { ph[2 * s2][0], ph[2 * s2][1],
                                   ph[2 * s2 + 1][0], ph[2 * s2 + 1][1] };
                const char* vcol = Vs + (32 * c + 16 * s2 + 2 * gk) * 2;
                #pragma unroll
                for (int n = 0; n < 8; n++) {
                    const char* vr = vcol + (8 * n + gm) * (PADH * 2);
                    uint32_t bv[2];
                    bv[0] = *(const uint32_t*)(vr);
                    bv[1] = *(const uint32_t*)(vr + 16);
                    mma_f16(o[n], af, bv);
                }
            }
        }
        __syncthreads();
    }

    // epilogue: write fp16 attention output (A operand of out-projection)
    float invA = 1.f / lA, invB = 1.f / lB;
    __half* dstA = g_atth + (size_t)(b * TT + rowA) * CC + h * DD;
    __half* dstB = g_atth + (size_t)(b * TT + rowA + 8) * CC + h * DD;
    #pragma unroll
    for (int n = 0; n < 8; n++) {
        int cix = 8 * n + 2 * gk;
        __half2 v0 = __floats2half2_rn(o[n][0] * invA, o[n][1] * invA);
        __half2 v1 = __floats2half2_rn(o[n][2] * invB, o[n][3] * invB);
        *(uint32_t*)(dstA + cix) = *(uint32_t*)&v0;
        *(uint32_t*)(dstB + cix) = *(uint32_t*)&v1;
    }
}

// ---------------------------------------------------------------------------
// Launch
// ---------------------------------------------------------------------------
extern "C" void kernel_launch(void* const* d_in, const int* in_sizes, int n_in,
                              void* d_out, int out_size)
{
    const float* x     = (const float*)d_in[0];
    const float* cosp  = (const float*)d_in[1];
    const float* sinp  = (const float*)d_in[2];
    const float* w_qkv = (const float*)d_in[3];
    const float* w_out = (const float*)d_in[4];
    float* out = (float*)d_out;

    float  *p_qkv;
    __half *p_xh, *p_wqkvh, *p_wouth, *p_atth;
    cudaGetSymbolAddress((void**)&p_qkv,   g_qkv);
    cudaGetSymbolAddress((void**)&p_xh,    g_xh);
    cudaGetSymbolAddress((void**)&p_wqkvh, g_wqkvh);
    cudaGetSymbolAddress((void**)&p_wouth, g_wouth);
    cudaGetSymbolAddress((void**)&p_atth,  g_atth);

    cudaFuncSetAttribute(gemm_f16,
                         cudaFuncAttributeMaxDynamicSharedMemorySize,
                         GEMMH_SMEM_BYTES);
    cudaFuncSetAttribute(attn_mma_h,
                         cudaFuncAttributeMaxDynamicSharedMemorySize,
                         ATTN_SMEM_BYTES);

    // 0) fp32 -> fp16 converts
    cvt_h<<<(MM * CC) / (8 * 256), 256>>>(x, p_xh, MM * CC);
    cvt_h<<<(NQKV * CC) / (8 * 256), 256>>>(w_qkv, p_wqkvh, NQKV * CC);
    cvt_h<<<(CC * CC) / (8 * 256), 256>>>(w_out, p_wouth, CC * CC);

    // 1) qkv = x @ w_qkv^T : M=4096, N=3072, K=1024 (fp16 in, fp32 out)
    {
        dim3 grid(NQKV / 128, MM / 128);
        gemm_f16<<<grid, 256, GEMMH_SMEM_BYTES>>>(p_xh, p_wqkvh, p_qkv, MM, NQKV, CC);
    }

    // 2a) RoPE q,k -> fp16 [bh][t][d]
    {
        int total = BB * TT * HH * 32;
        rope_scatter<<<(total + 255) / 256, 256>>>(cosp, sinp);
    }
    // 2b) V -> fp16 [bh][d][t]
    {
        dim3 grid(TT / 32, BB * HH);
        v_transpose<<<grid, 256>>>();
    }

    // 3) fp16 tensor-core causal flash attention
    {
        dim3 grid(TT / 128, BB * HH);
        attn_mma_h<<<grid, 256, ATTN_SMEM_BYTES>>>(0.125f * 1.44269504f);
    }

    // 4) out = att @ w_out^T : M=4096, N=1024, K=1024 (fp16 in, fp32 out)
    {
        dim3 grid(CC / 128, MM / 128);
        gemm_f16<<<grid, 256, GEMMH_SMEM_BYTES>>>(p_atth, p_wouth, out, MM, CC, CC);
    }
}

// round 8
// speedup vs baseline: 1.0863x; 1.0863x over previous
#include <cuda_runtime.h>
#include <cuda_fp16.h>
#include <cstdint>

// Problem constants
#define BB 2
#define TT 2048
#define HH 16
#define DD 64
#define CC 1024
#define MM (BB*TT)        // 4096 rows
#define NQKV (3*CC)       // 3072

// Scratch (device globals -- no allocation allowed)
__device__ float  g_qkv[MM * NQKV];        // [4096, 3072] fp32 qkv
__device__ __half g_xh[MM * CC];           // x in fp16
__device__ __half g_wqkvh[NQKV * CC];      // w_qkv in fp16
__device__ __half g_wouth[CC * CC];        // w_out in fp16
__device__ __half g_qh[BB*HH*TT*DD];       // [bh][t][d] fp16
__device__ __half g_kh[BB*HH*TT*DD];       // [bh][t][d] fp16
__device__ __half g_vh[BB*HH*DD*TT];       // [bh][d][t] fp16 (d-major)
__device__ __half g_atth[MM * CC];         // attention out, fp16 [B,T,C]

__device__ __forceinline__ float ex2(float x) {
    float y;
    asm("ex2.approx.ftz.f32 %0, %1;" : "=f"(y) : "f"(x));
    return y;
}

__device__ __forceinline__ void mma_f16(float* d, const uint32_t* a, const uint32_t* b) {
    asm volatile(
        "mma.sync.aligned.m16n8k16.row.col.f32.f16.f16.f32 "
        "{%0,%1,%2,%3},{%4,%5,%6,%7},{%8,%9},{%0,%1,%2,%3};\n"
        : "+f"(d[0]), "+f"(d[1]), "+f"(d[2]), "+f"(d[3])
        : "r"(a[0]), "r"(a[1]), "r"(a[2]), "r"(a[3]), "r"(b[0]), "r"(b[1]));
}

__device__ __forceinline__ void ldsm4(uint32_t* r, uint32_t addr) {
    asm volatile("ldmatrix.sync.aligned.m8n8.x4.shared.b16 {%0,%1,%2,%3}, [%4];"
                 : "=r"(r[0]), "=r"(r[1]), "=r"(r[2]), "=r"(r[3]) : "r"(addr));
}

__device__ __forceinline__ void cp16(uint32_t smem_addr, const void* gptr) {
    asm volatile("cp.async.cg.shared.global [%0], [%1], 16;\n"
                 :: "r"(smem_addr), "l"(gptr));
}

// ---------------------------------------------------------------------------
// fp32 -> fp16 convert (vectorized, 8 elems/thread)
// ---------------------------------------------------------------------------
__global__ __launch_bounds__(256) void cvt_h(
    const float* __restrict__ src, __half* __restrict__ dst, int n)
{
    int i = (blockIdx.x * blockDim.x + threadIdx.x) * 8;
    if (i >= n) return;
    float4 v0 = *(const float4*)(src + i);
    float4 v1 = *(const float4*)(src + i + 4);
    __half2 h0 = __floats2half2_rn(v0.x, v0.y);
    __half2 h1 = __floats2half2_rn(v0.z, v0.w);
    __half2 h2 = __floats2half2_rn(v1.x, v1.y);
    __half2 h3 = __floats2half2_rn(v1.z, v1.w);
    uint4 o;
    o.x = *(uint32_t*)&h0; o.y = *(uint32_t*)&h1;
    o.z = *(uint32_t*)&h2; o.w = *(uint32_t*)&h3;
    *(uint4*)(dst + i) = o;
}

// ---------------------------------------------------------------------------
// fp16 GEMM v3: C[m][n] = sum_k A[m][k] * B[n][k]  (fp32 out)
// Block tile 128x256, BK=32, 256 thr (8 warps = 2m x 4n, warp tile 64x64).
// ldmatrix.x4 fragment loads; rows padded to 40 halves (80B pitch) -> every
// 8-address LDSM phase and every cp.async store phase bank-conflict-free.
// 3-stage cp.async pipeline.
// ---------------------------------------------------------------------------
#define HBK 32
#define APITCH_B 80
#define ATILE_B (128*APITCH_B)            // 10240
#define BTILE_B (256*APITCH_B)            // 20480
#define HSTAGE_B (ATILE_B+BTILE_B)        // 30720
#define GEMMH_SMEM_BYTES (3*HSTAGE_B)     // 92160

__global__ __launch_bounds__(256) void gemm_f16_v3(
    const __half* __restrict__ A, const __half* __restrict__ Bm,
    float* __restrict__ C, int M, int N, int K)
{
    extern __shared__ char smc[];
    uint32_t smem_u32 = (uint32_t)__cvta_generic_to_shared(smc);

    const int tid  = threadIdx.x;
    const int lane = tid & 31;
    const int warp = tid >> 5;
    const int wm = warp & 1;              // 2 warps over m: 64 rows each
    const int wn = warp >> 1;             // 4 warps over n: 64 cols each
    const int m0 = blockIdx.y * 128;
    const int n0 = blockIdx.x * 256;
    const int gm = lane >> 2;
    const int gk = lane & 3;

    // ---- ldmatrix per-lane offsets ----
    const int g  = lane >> 3;
    const int lr = lane & 7;
    const uint32_t aoff = (uint32_t)((wm * 64 + (g & 1) * 8 + lr) * APITCH_B + (g >> 1) * 16);
    const uint32_t boff = (uint32_t)((wn * 64 + (g >> 1) * 8 + lr) * APITCH_B + (g & 1) * 16);

    // ---- cp.async loader mapping ----
    const int arow = tid & 127;
    const int ac   = tid >> 7;            // A chunks {ac, ac+2}
    const __half* Ag = A  + (size_t)(m0 + arow) * K + ac * 8;
    const __half* Bg = Bm + (size_t)(n0 + tid) * K;
    const uint32_t as_off = (uint32_t)(arow * APITCH_B + ac * 16);
    const uint32_t bs_off = (uint32_t)(ATILE_B + tid * APITCH_B);

    float acc[4][8][4];
    #pragma unroll
    for (int i = 0; i < 4; i++)
        #pragma unroll
        for (int j = 0; j < 8; j++)
            #pragma unroll
            for (int r = 0; r < 4; r++) acc[i][j][r] = 0.f;

    const int NI = K / HBK;

    auto issue = [&](int s, int kt) {
        uint32_t ab = smem_u32 + s * HSTAGE_B + as_off;
        const __half* asrc = Ag + kt * HBK;
        cp16(ab,      asrc);
        cp16(ab + 32, asrc + 16);
        uint32_t bb = smem_u32 + s * HSTAGE_B + bs_off;
        const __half* bsrc = Bg + kt * HBK;
        #pragma unroll
        for (int c = 0; c < 4; c++)
            cp16(bb + c * 16, bsrc + c * 8);
    };

    issue(0, 0);
    asm volatile("cp.async.commit_group;\n");
    if (NI > 1) issue(1, 1);
    asm volatile("cp.async.commit_group;\n");

    for (int it = 0; it < NI; it++) {
        __syncthreads();
        if (it + 2 < NI) issue((it + 2) % 3, it + 2);
        asm volatile("cp.async.commit_group;\n");
        asm volatile("cp.async.wait_group 2;\n");
        __syncthreads();

        const uint32_t stg = smem_u32 + (it % 3) * HSTAGE_B;
        const uint32_t abase = stg + aoff;
        const uint32_t bbase = stg + ATILE_B + boff;

        #pragma unroll
        for (int s = 0; s < 2; s++) {      // k-steps of 16
            uint32_t af[4][4];
            #pragma unroll
            for (int i = 0; i < 4; i++)
                ldsm4(af[i], abase + i * (16 * APITCH_B) + s * 32);
            uint32_t bf[4][4];
            #pragma unroll
            for (int jj = 0; jj < 4; jj++)
                ldsm4(bf[jj], bbase + jj * (16 * APITCH_B) + s * 32);

            #pragma unroll
            for (int i = 0; i < 4; i++)
                #pragma unroll
                for (int jj = 0; jj < 4; jj++) {
                    mma_f16(acc[i][2 * jj],     af[i], &bf[jj][0]);
                    mma_f16(acc[i][2 * jj + 1], af[i], &bf[jj][2]);
                }
        }
    }

    #pragma unroll
    for (int i = 0; i < 4; i++) {
        #pragma unroll
        for (int j = 0; j < 8; j++) {
            float* a = acc[i][j];
            int r = m0 + wm * 64 + 16 * i + gm;
            int c = n0 + wn * 64 + 8 * j + (gk << 1);
            float2 v0 = {a[0], a[1]};
            float2 v1 = {a[2], a[3]};
            *(float2*)(C + (size_t)r * N + c) = v0;
            *(float2*)(C + (size_t)(r + 8) * N + c) = v1;
        }
    }
}

// ---------------------------------------------------------------------------
// RoPE + scatter q,k -> fp16 [bh][t][d].
// ---------------------------------------------------------------------------
__global__ __launch_bounds__(256) void rope_scatter(
    const float* __restrict__ cosp, const float* __restrict__ sinp)
{
    int idx = blockIdx.x * blockDim.x + threadIdx.x;
    if (idx >= BB * TT * HH * 32) return;
    int d = idx & 31;
    int h = (idx >> 5) & (HH - 1);
    int t = (idx >> 9) & (TT - 1);
    int b = idx >> 20;

    const float* row = g_qkv + (size_t)(b * TT + t) * NQKV;
    int base = h * DD + d;

    float c0 = cosp[t * DD + d],      c1 = cosp[t * DD + d + 32];
    float s0 = sinp[t * DD + d],      s1 = sinp[t * DD + d + 32];

    float q0 = row[base],            q1 = row[base + 32];
    float k0 = row[CC + base],       k1 = row[CC + base + 32];

    size_t hoff = ((size_t)(b * HH + h) * TT + t) * DD + d;
    g_qh[hoff]      = __float2half(q0 * c0 - q1 * s0);
    g_qh[hoff + 32] = __float2half(q1 * c1 + q0 * s1);
    g_kh[hoff]      = __float2half(k0 * c0 - k1 * s0);
    g_kh[hoff + 32] = __float2half(k1 * c1 + k0 * s1);
}

// ---------------------------------------------------------------------------
// V transpose: g_qkv v-part [b,t,h*64+d] -> g_vh [bh][d][t] fp16.
// ---------------------------------------------------------------------------
__global__ __launch_bounds__(256) void v_transpose()
{
    __shared__ __half s[64][40];

    const int bh = blockIdx.y;
    const int b = bh >> 4, h = bh & 15;
    const int t0 = blockIdx.x * 32;
    const int tid = threadIdx.x;

    {
        int t = tid >> 3;
        int d8 = (tid & 7) << 3;
        const float* src = g_qkv + (size_t)(b * TT + t0 + t) * NQKV + 2 * CC + h * DD + d8;
        float4 v0 = *(const float4*)(src);
        float4 v1 = *(const float4*)(src + 4);
        s[d8 + 0][t] = __float2half(v0.x);
        s[d8 + 1][t] = __float2half(v0.y);
        s[d8 + 2][t] = __float2half(v0.z);
        s[d8 + 3][t] = __float2half(v0.w);
        s[d8 + 4][t] = __float2half(v1.x);
        s[d8 + 5][t] = __float2half(v1.y);
        s[d8 + 6][t] = __float2half(v1.z);
        s[d8 + 7][t] = __float2half(v1.w);
    }
    __syncthreads();

    {
        int d = tid >> 2;
        int tq = (tid & 3) << 3;
        uint4 v = *(const uint4*)&s[d][tq];
        __half* dst = g_vh + ((size_t)bh * DD + d) * TT + t0 + tq;
        *(uint4*)dst = v;
    }
}

// ---------------------------------------------------------------------------
// fp16 tensor-core causal flash attention (fp16 epilogue).
// ---------------------------------------------------------------------------
#define KT 64
#define PADH 72
#define KTILE_B (KT*PADH*2)          // 9216 bytes
#define STAGE_B (2*KTILE_B)
#define ATTN_SMEM_BYTES (2*STAGE_B)  // 36864

__global__ __launch_bounds__(256, 2) void attn_mma_h(float kscale)
{
    const int bh = blockIdx.y;
    const int q0 = (gridDim.x - 1 - blockIdx.x) * 128;
    const int b = bh >> 4, h = bh & 15;
    const int tid = threadIdx.x;
    const int lane = tid & 31;
    const int w = tid >> 5;
    const int gm = lane >> 2;
    const int gk = lane & 3;

    const __half* Qp = g_qh + (size_t)bh * TT * DD;
    const __half* Kp = g_kh + (size_t)bh * TT * DD;
    const __half* Vp = g_vh + (size_t)bh * DD * TT;

    extern __shared__ char smc[];
    uint32_t smem_u32 = (uint32_t)__cvta_generic_to_shared(smc);

    const int rowA = q0 + w * 16 + gm;
    const int wrow_lo = q0 + w * 16;
    const int wrow_hi = wrow_lo + 15;

    uint32_t qf[4][4];
    #pragma unroll
    for (int s = 0; s < 4; s++) {
        const __half* r0 = Qp + (size_t)rowA * DD + 16 * s + 2 * gk;
        const __half* r1 = Qp + (size_t)(rowA + 8) * DD + 16 * s + 2 * gk;
        qf[s][0] = *(const uint32_t*)r0;
        qf[s][1] = *(const uint32_t*)r1;
        qf[s][2] = *(const uint32_t*)(r0 + 8);
        qf[s][3] = *(const uint32_t*)(r1 + 8);
    }

    float o[8][4];
    #pragma unroll
    for (int n = 0; n < 8; n++)
        #pragma unroll
        for (int r = 0; r < 4; r++) o[n][r] = 0.f;
    float mA = -1e30f, mB = -1e30f, lA = 0.f, lB = 0.f;

    const int ntiles = (q0 + 128) / KT;

    const int ldrow = tid & 63;
    const int ldc2 = tid >> 6;
    auto issueKV = [&](int jt, int buf) {
        const char* kg = (const char*)(Kp + (size_t)jt * KT * DD);
        const char* vg = (const char*)(Vp + jt * KT);
        uint32_t kb = smem_u32 + buf * STAGE_B;
        uint32_t vb = kb + KTILE_B;
        uint32_t so = (uint32_t)(ldrow * (PADH * 2) + ldc2 * 16);
        cp16(kb + so,      kg + ldrow * 128 + ldc2 * 16);
        cp16(kb + so + 64, kg + ldrow * 128 + ldc2 * 16 + 64);
        cp16(vb + so,      vg + (size_t)ldrow * (TT * 2) + ldc2 * 16);
        cp16(vb + so + 64, vg + (size_t)ldrow * (TT * 2) + ldc2 * 16 + 64);
    };

    issueKV(0, 0);
    asm volatile("cp.async.commit_group;\n");

    for (int jt = 0; jt < ntiles; jt++) {
        if (jt + 1 < ntiles) {
            issueKV(jt + 1, (jt + 1) & 1);
            asm volatile("cp.async.commit_group;\n");
            asm volatile("cp.async.wait_group 1;\n");
        } else {
            asm volatile("cp.async.wait_group 0;\n");
        }
        __syncthreads();

        const char* Ks = smc + (jt & 1) * STAGE_B;
        const char* Vs = Ks + KTILE_B;
        const int j0 = jt * KT;

        #pragma unroll
        for (int c = 0; c < 2; c++) {
            const int c0 = j0 + 32 * c;
            if (c0 > wrow_hi) break;

            float sf[4][4];
            #pragma unroll
            for (int j = 0; j < 4; j++) {
                #pragma unroll
                for (int r = 0; r < 4; r++) sf[j][r] = 0.f;
                const char* kr = Ks + (32 * c + 8 * j + gm) * (PADH * 2) + 4 * gk;
                #pragma unroll
                for (int s = 0; s < 4; s++) {
                    uint32_t bq[2];
                    bq[0] = *(const uint32_t*)(kr + 32 * s);
                    bq[1] = *(const uint32_t*)(kr + 32 * s + 16);
                    mma_f16(sf[j], qf[s], bq);
                }
            }

            const bool needmask = (c0 + 31 > wrow_lo);
            float mxA = -1e30f, mxB = -1e30f;
            #pragma unroll
            for (int j = 0; j < 4; j++) {
                #pragma unroll
                for (int e = 0; e < 2; e++) {
                    int col = c0 + 8 * j + 2 * gk + e;
                    float v0 = sf[j][e] * kscale;
                    float v1 = sf[j][2 + e] * kscale;
                    if (needmask) {
                        if (col > rowA)     v0 = -1e30f;
                        if (col > rowA + 8) v1 = -1e30f;
                    }
                    sf[j][e] = v0; sf[j][2 + e] = v1;
                    mxA = fmaxf(mxA, v0); mxB = fmaxf(mxB, v1);
                }
            }
            mxA = fmaxf(mxA, __shfl_xor_sync(0xffffffffu, mxA, 1));
            mxA = fmaxf(mxA, __shfl_xor_sync(0xffffffffu, mxA, 2));
            mxB = fmaxf(mxB, __shfl_xor_sync(0xffffffffu, mxB, 1));
            mxB = fmaxf(mxB, __shfl_xor_sync(0xffffffffu, mxB, 2));

            float nmA = fmaxf(mA, mxA), nmB = fmaxf(mB, mxB);
            float aA = ex2(mA - nmA), aB = ex2(mB - nmB);
            mA = nmA; mB = nmB;

            #pragma unroll
            for (int n = 0; n < 8; n++) {
                o[n][0] *= aA; o[n][1] *= aA;
                o[n][2] *= aB; o[n][3] *= aB;
            }
            lA *= aA; lB *= aB;

            uint32_t ph[4][2];
            float slA = 0.f, slB = 0.f;
            #pragma unroll
            for (int j = 0; j < 4; j++) {
                float p0 = ex2(sf[j][0] - mA);
                float p1 = ex2(sf[j][1] - mA);
                float p2 = ex2(sf[j][2] - mB);
                float p3 = ex2(sf[j][3] - mB);
                slA += p0 + p1; slB += p2 + p3;
                __half2 h01 = __floats2half2_rn(p0, p1);
                __half2 h23 = __floats2half2_rn(p2, p3);
                ph[j][0] = *(const uint32_t*)&h01;
                ph[j][1] = *(const uint32_t*)&h23;
            }
            slA += __shfl_xor_sync(0xffffffffu, slA, 1);
            slA += __shfl_xor_sync(0xffffffffu, slA, 2);
            slB += __shfl_xor_sync(0xffffffffu, slB, 1);
            slB += __shfl_xor_sync(0xffffffffu, slB, 2);
            lA += slA; lB += slB;

            #pragma unroll
            for (int s2 = 0; s2 < 2; s2++) {
                uint32_t af[4] = { ph[2 * s2][0], ph[2 * s2][1],
                                   ph[2 * s2 + 1][0], ph[2 * s2 + 1][1] };
                const char* vcol = Vs + (32 * c + 16 * s2 + 2 * gk) * 2;
                #pragma unroll
                for (int n = 0; n < 8; n++) {
                    const char* vr = vcol + (8 * n + gm) * (PADH * 2);
                    uint32_t bv[2];
                    bv[0] = *(const uint32_t*)(vr);
                    bv[1] = *(const uint32_t*)(vr + 16);
                    mma_f16(o[n], af, bv);
                }
            }
        }
        __syncthreads();
    }

    float invA = 1.f / lA, invB = 1.f / lB;
    __half* dstA = g_atth + (size_t)(b * TT + rowA) * CC + h * DD;
    __half* dstB = g_atth + (size_t)(b * TT + rowA + 8) * CC + h * DD;
    #pragma unroll
    for (int n = 0; n < 8; n++) {
        int cix = 8 * n + 2 * gk;
        __half2 v0 = __floats2half2_rn(o[n][0] * invA, o[n][1] * invA);
        __half2 v1 = __floats2half2_rn(o[n][2] * invB, o[n][3] * invB);
        *(uint32_t*)(dstA + cix) = *(uint32_t*)&v0;
        *(uint32_t*)(dstB + cix) = *(uint32_t*)&v1;
    }
}

// ---------------------------------------------------------------------------
// Launch
// ---------------------------------------------------------------------------
extern "C" void kernel_launch(void* const* d_in, const int* in_sizes, int n_in,
                              void* d_out, int out_size)
{
    const float* x     = (const float*)d_in[0];
    const float* cosp  = (const float*)d_in[1];
    const float* sinp  = (const float*)d_in[2];
    const float* w_qkv = (const float*)d_in[3];
    const float* w_out = (const float*)d_in[4];
    float* out = (float*)d_out;

    float  *p_qkv;
    __half *p_xh, *p_wqkvh, *p_wouth, *p_atth;
    cudaGetSymbolAddress((void**)&p_qkv,   g_qkv);
    cudaGetSymbolAddress((void**)&p_xh,    g_xh);
    cudaGetSymbolAddress((void**)&p_wqkvh, g_wqkvh);
    cudaGetSymbolAddress((void**)&p_wouth, g_wouth);
    cudaGetSymbolAddress((void**)&p_atth,  g_atth);

    cudaFuncSetAttribute(gemm_f16_v3,
                         cudaFuncAttributeMaxDynamicSharedMemorySize,
                         GEMMH_SMEM_BYTES);
    cudaFuncSetAttribute(attn_mma_h,
                         cudaFuncAttributeMaxDynamicSharedMemorySize,
                         ATTN_SMEM_BYTES);

    // 0) fp32 -> fp16 converts
    cvt_h<<<(MM * CC) / (8 * 256), 256>>>(x, p_xh, MM * CC);
    cvt_h<<<(NQKV * CC) / (8 * 256), 256>>>(w_qkv, p_wqkvh, NQKV * CC);
    cvt_h<<<(CC * CC) / (8 * 256), 256>>>(w_out, p_wouth, CC * CC);

    // 1) qkv = x @ w_qkv^T : M=4096, N=3072, K=1024 (fp16 in, fp32 out)
    {
        dim3 grid(NQKV / 256, MM / 128);
        gemm_f16_v3<<<grid, 256, GEMMH_SMEM_BYTES>>>(p_xh, p_wqkvh, p_qkv, MM, NQKV, CC);
    }

    // 2a) RoPE q,k -> fp16 [bh][t][d]
    {
        int total = BB * TT * HH * 32;
        rope_scatter<<<(total + 255) / 256, 256>>>(cosp, sinp);
    }
    // 2b) V -> fp16 [bh][d][t]
    {
        dim3 grid(TT / 32, BB * HH);
        v_transpose<<<grid, 256>>>();
    }

    // 3) fp16 tensor-core causal flash attention
    {
        dim3 grid(TT / 128, BB * HH);
        attn_mma_h<<<grid, 256, ATTN_SMEM_BYTES>>>(0.125f * 1.44269504f);
    }

    // 4) out = att @ w_out^T : M=4096, N=1024, K=1024 (fp16 in, fp32 out)
    {
        dim3 grid(CC / 256, MM / 128);
        gemm_f16_v3<<<grid, 256, GEMMH_SMEM_BYTES>>>(p_atth, p_wouth, out, MM, CC, CC);
    }
}

// round 9
// speedup vs baseline: 1.6980x; 1.5631x over previous
#include <cuda_runtime.h>
#include <cuda.h>
#include <cuda_fp16.h>
#include <cstdint>

// Problem constants
#define BB 2
#define TT 2048
#define HH 16
#define DD 64
#define CC 1024
#define MM (BB*TT)        // 4096 rows
#define NQKV (3*CC)       // 3072

// Scratch (device globals -- no allocation allowed)
__device__ float  g_qkv[MM * NQKV];        // [4096, 3072] fp32 qkv
__device__ __half g_xh[MM * CC];           // x in fp16
__device__ __half g_wqkvh[NQKV * CC];      // w_qkv in fp16
__device__ __half g_wouth[CC * CC];        // w_out in fp16
__device__ __half g_qh[BB*HH*TT*DD];       // [bh][t][d] fp16
__device__ __half g_kh[BB*HH*TT*DD];       // [bh][t][d] fp16
__device__ __half g_vh[BB*HH*DD*TT];       // [bh][d][t] fp16 (d-major)
__device__ __half g_atth[MM * CC];         // attention out, fp16 [B,T,C]

__device__ __forceinline__ float ex2(float x) {
    float y;
    asm("ex2.approx.ftz.f32 %0, %1;" : "=f"(y) : "f"(x));
    return y;
}

__device__ __forceinline__ void mma_f16(float* d, const uint32_t* a, const uint32_t* b) {
    asm volatile(
        "mma.sync.aligned.m16n8k16.row.col.f32.f16.f16.f32 "
        "{%0,%1,%2,%3},{%4,%5,%6,%7},{%8,%9},{%0,%1,%2,%3};\n"
        : "+f"(d[0]), "+f"(d[1]), "+f"(d[2]), "+f"(d[3])
        : "r"(a[0]), "r"(a[1]), "r"(a[2]), "r"(a[3]), "r"(b[0]), "r"(b[1]));
}

__device__ __forceinline__ void ldsm4(uint32_t* r, uint32_t addr) {
    asm volatile("ldmatrix.sync.aligned.m8n8.x4.shared.b16 {%0,%1,%2,%3}, [%4];"
                 : "=r"(r[0]), "=r"(r[1]), "=r"(r[2]), "=r"(r[3]) : "r"(addr));
}

__device__ __forceinline__ void mbar_init(uint32_t addr, uint32_t cnt) {
    asm volatile("mbarrier.init.shared.b64 [%0], %1;" :: "r"(addr), "r"(cnt) : "memory");
}
__device__ __forceinline__ void mbar_expect_tx(uint32_t addr, uint32_t bytes) {
    asm volatile("mbarrier.arrive.expect_tx.shared.b64 _, [%0], %1;"
                 :: "r"(addr), "r"(bytes) : "memory");
}
__device__ __forceinline__ void mbar_wait(uint32_t addr, uint32_t parity) {
    asm volatile(
        "{\n\t.reg .pred P;\n"
        "W:\n\tmbarrier.try_wait.parity.acquire.cta.shared::cta.b64 P, [%0], %1, 0x989680;\n"
        "\t@P bra D;\n\tbra W;\nD:\n\t}"
        :: "r"(addr), "r"(parity) : "memory");
}
__device__ __forceinline__ void tma2d(uint32_t smem, const CUtensorMap* map,
                                      int x, int y, uint32_t bar) {
    asm volatile(
        "cp.async.bulk.tensor.2d.shared::cta.global.tile.mbarrier::complete_tx::bytes "
        "[%0], [%1, {%2, %3}], [%4];"
        :: "r"(smem), "l"(map), "r"(x), "r"(y), "r"(bar) : "memory");
}
__device__ __forceinline__ void tma3d(uint32_t smem, const CUtensorMap* map,
                                      int x, int y, int z, uint32_t bar) {
    asm volatile(
        "cp.async.bulk.tensor.3d.shared::cta.global.tile.mbarrier::complete_tx::bytes "
        "[%0], [%1, {%2, %3, %4}], [%5];"
        :: "r"(smem), "l"(map), "r"(x), "r"(y), "r"(z), "r"(bar) : "memory");
}

// ---------------------------------------------------------------------------
// fp32 -> fp16 convert (vectorized, 8 elems/thread)
// ---------------------------------------------------------------------------
__global__ __launch_bounds__(256) void cvt_h(
    const float* __restrict__ src, __half* __restrict__ dst, int n)
{
    int i = (blockIdx.x * blockDim.x + threadIdx.x) * 8;
    if (i >= n) return;
    float4 v0 = *(const float4*)(src + i);
    float4 v1 = *(const float4*)(src + i + 4);
    __half2 h0 = __floats2half2_rn(v0.x, v0.y);
    __half2 h1 = __floats2half2_rn(v0.z, v0.w);
    __half2 h2 = __floats2half2_rn(v1.x, v1.y);
    __half2 h3 = __floats2half2_rn(v1.z, v1.w);
    uint4 o;
    o.x = *(uint32_t*)&h0; o.y = *(uint32_t*)&h1;
    o.z = *(uint32_t*)&h2; o.w = *(uint32_t*)&h3;
    *(uint4*)(dst + i) = o;
}

// ---------------------------------------------------------------------------
// TMA fp16 GEMM: C[m][n] = sum_k A[m][k]*B[n][k]  (fp32 out)
// Block 128x128, BK=64, 256 thr (8 warps, 64x32 each), 3-stage TMA+mbarrier.
// SW128 swizzled tiles (128B rows): granule ^= row&7.
// ---------------------------------------------------------------------------
#define GS 3
#define GA_B 16384
#define GSTG (2*GA_B)                       // 32768 per stage (A+B)
#define GEMM_SMEM (1024 + GS*GSTG)          // 99328

__global__ __launch_bounds__(256, 2) void gemm_tma(
    const __grid_constant__ CUtensorMap mA,
    const __grid_constant__ CUtensorMap mB,
    float* __restrict__ C, int N, int K)
{
    extern __shared__ __align__(128) char smc[];
    uint32_t sb = (uint32_t)__cvta_generic_to_shared(smc);
    const uint32_t mbar = sb;
    const uint32_t tiles = sb + 1024;

    const int tid  = threadIdx.x;
    const int lane = tid & 31;
    const int warp = tid >> 5;
    const int wm = warp & 1;                // 64 rows each
    const int wn = warp >> 1;               // 32 cols each
    const int m0 = blockIdx.y * 128;
    const int n0 = blockIdx.x * 128;
    const int g  = lane >> 3;
    const int lr = lane & 7;
    const int gm = lane >> 2;
    const int gk = lane & 3;

    const int NI = K / 64;

    if (tid == 0) {
        #pragma unroll
        for (int s = 0; s < GS; s++) mbar_init(mbar + 8 * s, 1);
    }
    __syncthreads();

    auto prod = [&](int kt, int s) {
        uint32_t bar = mbar + 8 * s;
        mbar_expect_tx(bar, GSTG);
        tma2d(tiles + s * GSTG,        &mA, kt * 64, m0, bar);
        tma2d(tiles + s * GSTG + GA_B, &mB, kt * 64, n0, bar);
    };
    if (tid == 0) {
        prod(0, 0);
        prod(1, 1);
        prod(2, 2);
    }

    // ldmatrix row bases (within a tile): A rows wm*64+16i+(g&1)*8+lr,
    // B rows wn*32+16jj+(g>>1)*8+lr; swizzle XOR key = lr.
    uint32_t arow[4], brow[2];
    #pragma unroll
    for (int i = 0; i < 4; i++)
        arow[i] = (uint32_t)((wm * 64 + 16 * i + (g & 1) * 8 + lr) * 128);
    #pragma unroll
    for (int jj = 0; jj < 2; jj++)
        brow[jj] = (uint32_t)(GA_B + (wn * 32 + 16 * jj + (g >> 1) * 8 + lr) * 128);

    float acc[16][4];
    #pragma unroll
    for (int t = 0; t < 16; t++)
        #pragma unroll
        for (int r = 0; r < 4; r++) acc[t][r] = 0.f;

    for (int it = 0; it < NI; it++) {
        const int s = it % GS;
        const uint32_t ph = (uint32_t)((it / GS) & 1);
        mbar_wait(mbar + 8 * s, ph);

        const uint32_t stg = tiles + s * GSTG;
        #pragma unroll
        for (int ks = 0; ks < 4; ks++) {
            uint32_t af[4][4];
            const uint32_t ag = (uint32_t)(((2 * ks + (g >> 1)) ^ lr) << 4);
            #pragma unroll
            for (int i = 0; i < 4; i++)
                ldsm4(af[i], stg + arow[i] + ag);
            uint32_t bf[2][4];
            const uint32_t bg = (uint32_t)(((2 * ks + (g & 1)) ^ lr) << 4);
            #pragma unroll
            for (int jj = 0; jj < 2; jj++)
                ldsm4(bf[jj], stg + brow[jj] + bg);

            #pragma unroll
            for (int i = 0; i < 4; i++)
                #pragma unroll
                for (int jj = 0; jj < 2; jj++) {
                    mma_f16(acc[i * 4 + 2 * jj],     af[i], &bf[jj][0]);
                    mma_f16(acc[i * 4 + 2 * jj + 1], af[i], &bf[jj][2]);
                }
        }
        __syncthreads();
        if (tid == 0 && it + GS < NI) prod(it + GS, s);
    }

    #pragma unroll
    for (int i = 0; i < 4; i++) {
        #pragma unroll
        for (int nn = 0; nn < 4; nn++) {
            float* a = acc[i * 4 + nn];
            int r = m0 + wm * 64 + 16 * i + gm;
            int c = n0 + wn * 32 + 8 * nn + (gk << 1);
            float2 v0 = {a[0], a[1]};
            float2 v1 = {a[2], a[3]};
            *(float2*)(C + (size_t)r * N + c) = v0;
            *(float2*)(C + (size_t)(r + 8) * N + c) = v1;
        }
    }
}

// ---------------------------------------------------------------------------
// RoPE + scatter q,k -> fp16 [bh][t][d].
// ---------------------------------------------------------------------------
__global__ __launch_bounds__(256) void rope_scatter(
    const float* __restrict__ cosp, const float* __restrict__ sinp)
{
    int idx = blockIdx.x * blockDim.x + threadIdx.x;
    if (idx >= BB * TT * HH * 32) return;
    int d = idx & 31;
    int h = (idx >> 5) & (HH - 1);
    int t = (idx >> 9) & (TT - 1);
    int b = idx >> 20;

    const float* row = g_qkv + (size_t)(b * TT + t) * NQKV;
    int base = h * DD + d;

    float c0 = cosp[t * DD + d],      c1 = cosp[t * DD + d + 32];
    float s0 = sinp[t * DD + d],      s1 = sinp[t * DD + d + 32];

    float q0 = row[base],            q1 = row[base + 32];
    float k0 = row[CC + base],       k1 = row[CC + base + 32];

    size_t hoff = ((size_t)(b * HH + h) * TT + t) * DD + d;
    g_qh[hoff]      = __float2half(q0 * c0 - q1 * s0);
    g_qh[hoff + 32] = __float2half(q1 * c1 + q0 * s1);
    g_kh[hoff]      = __float2half(k0 * c0 - k1 * s0);
    g_kh[hoff + 32] = __float2half(k1 * c1 + k0 * s1);
}

// ---------------------------------------------------------------------------
// V transpose: g_qkv v-part [b,t,h*64+d] -> g_vh [bh][d][t] fp16.
// ---------------------------------------------------------------------------
__global__ __launch_bounds__(256) void v_transpose()
{
    __shared__ __half s[64][40];

    const int bh = blockIdx.y;
    const int b = bh >> 4, h = bh & 15;
    const int t0 = blockIdx.x * 32;
    const int tid = threadIdx.x;

    {
        int t = tid >> 3;
        int d8 = (tid & 7) << 3;
        const float* src = g_qkv + (size_t)(b * TT + t0 + t) * NQKV + 2 * CC + h * DD + d8;
        float4 v0 = *(const float4*)(src);
        float4 v1 = *(const float4*)(src + 4);
        s[d8 + 0][t] = __float2half(v0.x);
        s[d8 + 1][t] = __float2half(v0.y);
        s[d8 + 2][t] = __float2half(v0.z);
        s[d8 + 3][t] = __float2half(v0.w);
        s[d8 + 4][t] = __float2half(v1.x);
        s[d8 + 5][t] = __float2half(v1.y);
        s[d8 + 6][t] = __float2half(v1.z);
        s[d8 + 7][t] = __float2half(v1.w);
    }
    __syncthreads();

    {
        int d = tid >> 2;
        int tq = (tid & 3) << 3;
        uint4 v = *(const uint4*)&s[d][tq];
        __half* dst = g_vh + ((size_t)bh * DD + d) * TT + t0 + tq;
        *(uint4*)dst = v;
    }
}

// ---------------------------------------------------------------------------
// TMA fp16 causal flash attention.
// K tile: [64 keys][128B d, SW128]; V tile: [64 d][128B t, SW128].
// 2-stage TMA pipeline; scalar frag loads swizzle-adjusted (conflict-free).
// ---------------------------------------------------------------------------
#define AKT_B 8192
#define ASTG (2*AKT_B)                      // K+V = 16384
#define ATTN_SMEM (1024 + 2*ASTG)           // 33792

__global__ __launch_bounds__(256, 2) void attn_tma(
    const __grid_constant__ CUtensorMap mK,
    const __grid_constant__ CUtensorMap mV,
    float kscale)
{
    const int bh = blockIdx.y;
    const int q0 = (gridDim.x - 1 - blockIdx.x) * 128;
    const int b = bh >> 4, h = bh & 15;
    const int tid = threadIdx.x;
    const int lane = tid & 31;
    const int w = tid >> 5;
    const int gm = lane >> 2;
    const int gk = lane & 3;

    const __half* Qp = g_qh + (size_t)bh * TT * DD;

    extern __shared__ __align__(128) char smc[];
    uint32_t sb = (uint32_t)__cvta_generic_to_shared(smc);
    const uint32_t mbar = sb;
    char* tiles = smc + 1024;

    const int rowA = q0 + w * 16 + gm;
    const int wrow_lo = q0 + w * 16;
    const int wrow_hi = wrow_lo + 15;

    const int ntiles = (q0 + 128) / 64;

    if (tid == 0) { mbar_init(mbar, 1); mbar_init(mbar + 8, 1); }
    __syncthreads();

    const uint32_t tiles_u32 = sb + 1024;
    auto prod = [&](int jt, int s) {
        uint32_t bar = mbar + 8 * s;
        mbar_expect_tx(bar, ASTG);
        tma3d(tiles_u32 + s * ASTG,         &mK, 0, jt * 64, bh, bar);
        tma3d(tiles_u32 + s * ASTG + AKT_B, &mV, jt * 64, 0, bh, bar);
    };
    if (tid == 0) { prod(0, 0); prod(1, 1); }

    uint32_t qf[4][4];
    #pragma unroll
    for (int s = 0; s < 4; s++) {
        const __half* r0 = Qp + (size_t)rowA * DD + 16 * s + 2 * gk;
        const __half* r1 = Qp + (size_t)(rowA + 8) * DD + 16 * s + 2 * gk;
        qf[s][0] = *(const uint32_t*)r0;
        qf[s][1] = *(const uint32_t*)r1;
        qf[s][2] = *(const uint32_t*)(r0 + 8);
        qf[s][3] = *(const uint32_t*)(r1 + 8);
    }

    float o[8][4];
    #pragma unroll
    for (int n = 0; n < 8; n++)
        #pragma unroll
        for (int r = 0; r < 4; r++) o[n][r] = 0.f;
    float mA = -1e30f, mB = -1e30f, lA = 0.f, lB = 0.f;

    for (int jt = 0; jt < ntiles; jt++) {
        const int st = jt & 1;
        mbar_wait(mbar + 8 * st, (uint32_t)((jt >> 1) & 1));

        const char* Ks = tiles + st * ASTG;
        const char* Vs = Ks + AKT_B;
        const int j0 = jt * 64;

        #pragma unroll
        for (int c = 0; c < 2; c++) {
            const int c0 = j0 + 32 * c;
            if (c0 > wrow_hi) break;

            // ---- S = Q K^T (16x32), swizzled scalar B loads ----
            float sf[4][4];
            #pragma unroll
            for (int j = 0; j < 4; j++) {
                #pragma unroll
                for (int r = 0; r < 4; r++) sf[j][r] = 0.f;
                const char* kr = Ks + (32 * c + 8 * j + gm) * 128 + 4 * gk;
                #pragma unroll
                for (int s = 0; s < 4; s++) {
                    uint32_t bq[2];
                    bq[0] = *(const uint32_t*)(kr + (((2 * s)     ^ gm) << 4));
                    bq[1] = *(const uint32_t*)(kr + (((2 * s + 1) ^ gm) << 4));
                    mma_f16(sf[j], qf[s], bq);
                }
            }

            const bool needmask = (c0 + 31 > wrow_lo);
            float mxA = -1e30f, mxB = -1e30f;
            #pragma unroll
            for (int j = 0; j < 4; j++) {
                #pragma unroll
                for (int e = 0; e < 2; e++) {
                    int col = c0 + 8 * j + 2 * gk + e;
                    float v0 = sf[j][e] * kscale;
                    float v1 = sf[j][2 + e] * kscale;
                    if (needmask) {
                        if (col > rowA)     v0 = -1e30f;
                        if (col > rowA + 8) v1 = -1e30f;
                    }
                    sf[j][e] = v0; sf[j][2 + e] = v1;
                    mxA = fmaxf(mxA, v0); mxB = fmaxf(mxB, v1);
                }
            }
            mxA = fmaxf(mxA, __shfl_xor_sync(0xffffffffu, mxA, 1));
            mxA = fmaxf(mxA, __shfl_xor_sync(0xffffffffu, mxA, 2));
            mxB = fmaxf(mxB, __shfl_xor_sync(0xffffffffu, mxB, 1));
            mxB = fmaxf(mxB, __shfl_xor_sync(0xffffffffu, mxB, 2));

            float nmA = fmaxf(mA, mxA), nmB = fmaxf(mB, mxB);
            float aA = ex2(mA - nmA), aB = ex2(mB - nmB);
            mA = nmA; mB = nmB;

            #pragma unroll
            for (int n = 0; n < 8; n++) {
                o[n][0] *= aA; o[n][1] *= aA;
                o[n][2] *= aB; o[n][3] *= aB;
            }
            lA *= aA; lB *= aB;

            uint32_t phl[4][2];
            float slA = 0.f, slB = 0.f;
            #pragma unroll
            for (int j = 0; j < 4; j++) {
                float p0 = ex2(sf[j][0] - mA);
                float p1 = ex2(sf[j][1] - mA);
                float p2 = ex2(sf[j][2] - mB);
                float p3 = ex2(sf[j][3] - mB);
                slA += p0 + p1; slB += p2 + p3;
                __half2 h01 = __floats2half2_rn(p0, p1);
                __half2 h23 = __floats2half2_rn(p2, p3);
                phl[j][0] = *(const uint32_t*)&h01;
                phl[j][1] = *(const uint32_t*)&h23;
            }
            slA += __shfl_xor_sync(0xffffffffu, slA, 1);
            slA += __shfl_xor_sync(0xffffffffu, slA, 2);
            slB += __shfl_xor_sync(0xffffffffu, slB, 1);
            slB += __shfl_xor_sync(0xffffffffu, slB, 2);
            lA += slA; lB += slB;

            // ---- O += P V, swizzled scalar B loads from d-major V ----
            #pragma unroll
            for (int s2 = 0; s2 < 2; s2++) {
                uint32_t af[4] = { phl[2 * s2][0], phl[2 * s2][1],
                                   phl[2 * s2 + 1][0], phl[2 * s2 + 1][1] };
                const int gran = 4 * c + 2 * s2;
                #pragma unroll
                for (int n = 0; n < 8; n++) {
                    const char* vb = Vs + (8 * n + gm) * 128 + 4 * gk;
                    uint32_t bv[2];
                    bv[0] = *(const uint32_t*)(vb + (((gran)     ^ gm) << 4));
                    bv[1] = *(const uint32_t*)(vb + (((gran + 1) ^ gm) << 4));
                    mma_f16(o[n], af, bv);
                }
            }
        }
        __syncthreads();
        if (tid == 0 && jt + 2 < ntiles) prod(jt + 2, st);
    }

    float invA = 1.f / lA, invB = 1.f / lB;
    __half* dstA = g_atth + (size_t)(b * TT + rowA) * CC + h * DD;
    __half* dstB = g_atth + (size_t)(b * TT + rowA + 8) * CC + h * DD;
    #pragma unroll
    for (int n = 0; n < 8; n++) {
        int cix = 8 * n + 2 * gk;
        __half2 v0 = __floats2half2_rn(o[n][0] * invA, o[n][1] * invA);
        __half2 v1 = __floats2half2_rn(o[n][2] * invB, o[n][3] * invB);
        *(uint32_t*)(dstA + cix) = *(uint32_t*)&v0;
        *(uint32_t*)(dstB + cix) = *(uint32_t*)&v1;
    }
}

// ---------------------------------------------------------------------------
// Host: tensor-map encode via driver entry point (no -lcuda needed)
// ---------------------------------------------------------------------------
typedef CUresult (*PFN_tmap_encode)(
    CUtensorMap*, CUtensorMapDataType, cuuint32_t, void*,
    const cuuint64_t*, const cuuint64_t*, const cuuint32_t*, const cuuint32_t*,
    CUtensorMapInterleave, CUtensorMapSwizzle, CUtensorMapL2promotion,
    CUtensorMapFloatOOBfill);

static PFN_tmap_encode get_encoder() {
    void* fn = nullptr;
    cudaDriverEntryPointQueryResult qr;
    cudaGetDriverEntryPoint("cuTensorMapEncodeTiled", &fn, cudaEnableDefault, &qr);
    return (PFN_tmap_encode)fn;
}

static void enc2d(PFN_tmap_encode f, CUtensorMap* m, void* base,
                  uint64_t d0, uint64_t d1, uint32_t b0, uint32_t b1) {
    cuuint64_t dims[2] = {d0, d1};
    cuuint64_t str[1]  = {d0 * 2};
    cuuint32_t box[2]  = {b0, b1};
    cuuint32_t es[2]   = {1, 1};
    f(m, CU_TENSOR_MAP_DATA_TYPE_FLOAT16, 2, base, dims, str, box, es,
      CU_TENSOR_MAP_INTERLEAVE_NONE, CU_TENSOR_MAP_SWIZZLE_128B,
      CU_TENSOR_MAP_L2_PROMOTION_L2_128B, CU_TENSOR_MAP_FLOAT_OOB_FILL_NONE);
}

static void enc3d(PFN_tmap_encode f, CUtensorMap* m, void* base,
                  uint64_t d0, uint64_t d1, uint64_t d2,
                  uint32_t b0, uint32_t b1) {
    cuuint64_t dims[3] = {d0, d1, d2};
    cuuint64_t str[2]  = {d0 * 2, d0 * d1 * 2};
    cuuint32_t box[3]  = {b0, b1, 1};
    cuuint32_t es[3]   = {1, 1, 1};
    f(m, CU_TENSOR_MAP_DATA_TYPE_FLOAT16, 3, base, dims, str, box, es,
      CU_TENSOR_MAP_INTERLEAVE_NONE, CU_TENSOR_MAP_SWIZZLE_128B,
      CU_TENSOR_MAP_L2_PROMOTION_L2_128B, CU_TENSOR_MAP_FLOAT_OOB_FILL_NONE);
}

// ---------------------------------------------------------------------------
// Launch
// ---------------------------------------------------------------------------
extern "C" void kernel_launch(void* const* d_in, const int* in_sizes, int n_in,
                              void* d_out, int out_size)
{
    const float* x     = (const float*)d_in[0];
    const float* cosp  = (const float*)d_in[1];
    const float* sinp  = (const float*)d_in[2];
    const float* w_qkv = (const float*)d_in[3];
    const float* w_out = (const float*)d_in[4];
    float* out = (float*)d_out;

    float  *p_qkv;
    __half *p_xh, *p_wqkvh, *p_wouth, *p_qh, *p_kh, *p_vh, *p_atth;
    cudaGetSymbolAddress((void**)&p_qkv,   g_qkv);
    cudaGetSymbolAddress((void**)&p_xh,    g_xh);
    cudaGetSymbolAddress((void**)&p_wqkvh, g_wqkvh);
    cudaGetSymbolAddress((void**)&p_wouth, g_wouth);
    cudaGetSymbolAddress((void**)&p_qh,    g_qh);
    cudaGetSymbolAddress((void**)&p_kh,    g_kh);
    cudaGetSymbolAddress((void**)&p_vh,    g_vh);
    cudaGetSymbolAddress((void**)&p_atth,  g_atth);

    PFN_tmap_encode enc = get_encoder();

    CUtensorMap mX, mWqkv, mAtt, mWout, mK, mV;
    enc2d(enc, &mX,    p_xh,    CC, MM,   64, 128);   // A of qkv GEMM
    enc2d(enc, &mWqkv, p_wqkvh, CC, NQKV, 64, 128);   // B of qkv GEMM
    enc2d(enc, &mAtt,  p_atth,  CC, MM,   64, 128);   // A of out GEMM
    enc2d(enc, &mWout, p_wouth, CC, CC,   64, 128);   // B of out GEMM
    enc3d(enc, &mK, p_kh, DD, TT, BB * HH, 64, 64);   // K tiles [d][t][bh]
    enc3d(enc, &mV, p_vh, TT, DD, BB * HH, 64, 64);   // V tiles [t][d][bh]

    cudaFuncSetAttribute(gemm_tma,
                         cudaFuncAttributeMaxDynamicSharedMemorySize, GEMM_SMEM);
    cudaFuncSetAttribute(attn_tma,
                         cudaFuncAttributeMaxDynamicSharedMemorySize, ATTN_SMEM);

    // 0) fp32 -> fp16 converts
    cvt_h<<<(MM * CC) / (8 * 256), 256>>>(x, p_xh, MM * CC);
    cvt_h<<<(NQKV * CC) / (8 * 256), 256>>>(w_qkv, p_wqkvh, NQKV * CC);
    cvt_h<<<(CC * CC) / (8 * 256), 256>>>(w_out, p_wouth, CC * CC);

    // 1) qkv = x @ w_qkv^T : M=4096, N=3072, K=1024
    {
        dim3 grid(NQKV / 128, MM / 128);
        gemm_tma<<<grid, 256, GEMM_SMEM>>>(mX, mWqkv, p_qkv, NQKV, CC);
    }

    // 2a) RoPE q,k -> fp16 [bh][t][d]
    {
        int total = BB * TT * HH * 32;
        rope_scatter<<<(total + 255) / 256, 256>>>(cosp, sinp);
    }
    // 2b) V -> fp16 [bh][d][t]
    {
        dim3 grid(TT / 32, BB * HH);
        v_transpose<<<grid, 256>>>();
    }

    // 3) TMA fp16 causal flash attention
    {
        dim3 grid(TT / 128, BB * HH);
        attn_tma<<<grid, 256, ATTN_SMEM>>>(mK, mV, 0.125f * 1.44269504f);
    }

    // 4) out = att @ w_out^T : M=4096, N=1024, K=1024
    {
        dim3 grid(CC / 128, MM / 128);
        gemm_tma<<<grid, 256, GEMM_SMEM>>>(mAtt, mWout, out, CC, CC);
    }
}

// round 10
// speedup vs baseline: 1.7450x; 1.0277x over previous
#include <cuda_runtime.h>
#include <cuda.h>
#include <cuda_fp16.h>
#include <cstdint>

// Problem constants
#define BB 2
#define TT 2048
#define HH 16
#define DD 64
#define CC 1024
#define MM (BB*TT)        // 4096 rows
#define NQKV (3*CC)       // 3072

// Scratch (device globals -- no allocation allowed)
__device__ __half g_qkvh[MM * NQKV];       // [4096, 3072] fp16 qkv
__device__ __half g_xh[MM * CC];           // x in fp16
__device__ __half g_wqkvh[NQKV * CC];      // w_qkv in fp16
__device__ __half g_wouth[CC * CC];        // w_out in fp16
__device__ __half g_qh[BB*HH*TT*DD];       // [bh][t][d] fp16
__device__ __half g_kh[BB*HH*TT*DD];       // [bh][t][d] fp16
__device__ __half g_vh[BB*HH*DD*TT];       // [bh][d][t] fp16 (d-major)
__device__ __half g_atth[MM * CC];         // attention out, fp16 [B,T,C]

__device__ __forceinline__ float ex2(float x) {
    float y;
    asm("ex2.approx.ftz.f32 %0, %1;" : "=f"(y) : "f"(x));
    return y;
}

__device__ __forceinline__ void mma_f16(float* d, const uint32_t* a, const uint32_t* b) {
    asm volatile(
        "mma.sync.aligned.m16n8k16.row.col.f32.f16.f16.f32 "
        "{%0,%1,%2,%3},{%4,%5,%6,%7},{%8,%9},{%0,%1,%2,%3};\n"
        : "+f"(d[0]), "+f"(d[1]), "+f"(d[2]), "+f"(d[3])
        : "r"(a[0]), "r"(a[1]), "r"(a[2]), "r"(a[3]), "r"(b[0]), "r"(b[1]));
}

__device__ __forceinline__ void ldsm4(uint32_t* r, uint32_t addr) {
    asm volatile("ldmatrix.sync.aligned.m8n8.x4.shared.b16 {%0,%1,%2,%3}, [%4];"
                 : "=r"(r[0]), "=r"(r[1]), "=r"(r[2]), "=r"(r[3]) : "r"(addr));
}

__device__ __forceinline__ void mbar_init(uint32_t addr, uint32_t cnt) {
    asm volatile("mbarrier.init.shared.b64 [%0], %1;" :: "r"(addr), "r"(cnt) : "memory");
}
__device__ __forceinline__ void mbar_expect_tx(uint32_t addr, uint32_t bytes) {
    asm volatile("mbarrier.arrive.expect_tx.shared.b64 _, [%0], %1;"
                 :: "r"(addr), "r"(bytes) : "memory");
}
__device__ __forceinline__ void mbar_wait(uint32_t addr, uint32_t parity) {
    asm volatile(
        "{\n\t.reg .pred P;\n"
        "W:\n\tmbarrier.try_wait.parity.acquire.cta.shared::cta.b64 P, [%0], %1, 0x989680;\n"
        "\t@P bra D;\n\tbra W;\nD:\n\t}"
        :: "r"(addr), "r"(parity) : "memory");
}
__device__ __forceinline__ void tma2d(uint32_t smem, const CUtensorMap* map,
                                      int x, int y, uint32_t bar) {
    asm volatile(
        "cp.async.bulk.tensor.2d.shared::cta.global.tile.mbarrier::complete_tx::bytes "
        "[%0], [%1, {%2, %3}], [%4];"
        :: "r"(smem), "l"(map), "r"(x), "r"(y), "r"(bar) : "memory");
}
__device__ __forceinline__ void tma3d(uint32_t smem, const CUtensorMap* map,
                                      int x, int y, int z, uint32_t bar) {
    asm volatile(
        "cp.async.bulk.tensor.3d.shared::cta.global.tile.mbarrier::complete_tx::bytes "
        "[%0], [%1, {%2, %3, %4}], [%5];"
        :: "r"(smem), "l"(map), "r"(x), "r"(y), "r"(z), "r"(bar) : "memory");
}

// ---------------------------------------------------------------------------
// fp32 -> fp16 convert (vectorized, 8 elems/thread)
// ---------------------------------------------------------------------------
__global__ __launch_bounds__(256) void cvt_h(
    const float* __restrict__ src, __half* __restrict__ dst, int n)
{
    int i = (blockIdx.x * blockDim.x + threadIdx.x) * 8;
    if (i >= n) return;
    float4 v0 = *(const float4*)(src + i);
    float4 v1 = *(const float4*)(src + i + 4);
    __half2 h0 = __floats2half2_rn(v0.x, v0.y);
    __half2 h1 = __floats2half2_rn(v0.z, v0.w);
    __half2 h2 = __floats2half2_rn(v1.x, v1.y);
    __half2 h3 = __floats2half2_rn(v1.z, v1.w);
    uint4 o;
    o.x = *(uint32_t*)&h0; o.y = *(uint32_t*)&h1;
    o.z = *(uint32_t*)&h2; o.w = *(uint32_t*)&h3;
    *(uint4*)(dst + i) = o;
}

// ---------------------------------------------------------------------------
// TMA fp16 GEMM: C[m][n] = sum_k A[m][k]*B[n][k]; OutT = float or __half.
// Block 128x128, BK=64, 256 thr (8 warps, 64x32 each), 3-stage TMA+mbarrier.
// SW128 swizzled tiles (128B rows): granule ^= row&7.
// ---------------------------------------------------------------------------
#define GS 3
#define GA_B 16384
#define GSTG (2*GA_B)                       // 32768 per stage (A+B)
#define GEMM_SMEM (1024 + GS*GSTG)          // 99328

template <typename OutT>
__global__ __launch_bounds__(256, 2) void gemm_tma(
    const __grid_constant__ CUtensorMap mA,
    const __grid_constant__ CUtensorMap mB,
    OutT* __restrict__ C, int N, int K)
{
    extern __shared__ __align__(128) char smc[];
    uint32_t sb = (uint32_t)__cvta_generic_to_shared(smc);
    const uint32_t mbar = sb;
    const uint32_t tiles = sb + 1024;

    const int tid  = threadIdx.x;
    const int lane = tid & 31;
    const int warp = tid >> 5;
    const int wm = warp & 1;
    const int wn = warp >> 1;
    const int m0 = blockIdx.y * 128;
    const int n0 = blockIdx.x * 128;
    const int g  = lane >> 3;
    const int lr = lane & 7;
    const int gm = lane >> 2;
    const int gk = lane & 3;

    const int NI = K / 64;

    if (tid == 0) {
        #pragma unroll
        for (int s = 0; s < GS; s++) mbar_init(mbar + 8 * s, 1);
    }
    __syncthreads();

    auto prod = [&](int kt, int s) {
        uint32_t bar = mbar + 8 * s;
        mbar_expect_tx(bar, GSTG);
        tma2d(tiles + s * GSTG,        &mA, kt * 64, m0, bar);
        tma2d(tiles + s * GSTG + GA_B, &mB, kt * 64, n0, bar);
    };
    if (tid == 0) { prod(0, 0); prod(1, 1); prod(2, 2); }

    uint32_t arow[4], brow[2];
    #pragma unroll
    for (int i = 0; i < 4; i++)
        arow[i] = (uint32_t)((wm * 64 + 16 * i + (g & 1) * 8 + lr) * 128);
    #pragma unroll
    for (int jj = 0; jj < 2; jj++)
        brow[jj] = (uint32_t)(GA_B + (wn * 32 + 16 * jj + (g >> 1) * 8 + lr) * 128);

    float acc[16][4];
    #pragma unroll
    for (int t = 0; t < 16; t++)
        #pragma unroll
        for (int r = 0; r < 4; r++) acc[t][r] = 0.f;

    for (int it = 0; it < NI; it++) {
        const int s = it % GS;
        const uint32_t ph = (uint32_t)((it / GS) & 1);
        mbar_wait(mbar + 8 * s, ph);

        const uint32_t stg = tiles + s * GSTG;
        #pragma unroll
        for (int ks = 0; ks < 4; ks++) {
            uint32_t af[4][4];
            const uint32_t ag = (uint32_t)(((2 * ks + (g >> 1)) ^ lr) << 4);
            #pragma unroll
            for (int i = 0; i < 4; i++)
                ldsm4(af[i], stg + arow[i] + ag);
            uint32_t bf[2][4];
            const uint32_t bg = (uint32_t)(((2 * ks + (g & 1)) ^ lr) << 4);
            #pragma unroll
            for (int jj = 0; jj < 2; jj++)
                ldsm4(bf[jj], stg + brow[jj] + bg);

            #pragma unroll
            for (int i = 0; i < 4; i++)
                #pragma unroll
                for (int jj = 0; jj < 2; jj++) {
                    mma_f16(acc[i * 4 + 2 * jj],     af[i], &bf[jj][0]);
                    mma_f16(acc[i * 4 + 2 * jj + 1], af[i], &bf[jj][2]);
                }
        }
        __syncthreads();
        if (tid == 0 && it + GS < NI) prod(it + GS, s);
    }

    #pragma unroll
    for (int i = 0; i < 4; i++) {
        #pragma unroll
        for (int nn = 0; nn < 4; nn++) {
            float* a = acc[i * 4 + nn];
            int r = m0 + wm * 64 + 16 * i + gm;
            int c = n0 + wn * 32 + 8 * nn + (gk << 1);
            if constexpr (sizeof(OutT) == 4) {
                float2 v0 = {a[0], a[1]};
                float2 v1 = {a[2], a[3]};
                *(float2*)((float*)C + (size_t)r * N + c) = v0;
                *(float2*)((float*)C + (size_t)(r + 8) * N + c) = v1;
            } else {
                __half2 v0 = __floats2half2_rn(a[0], a[1]);
                __half2 v1 = __floats2half2_rn(a[2], a[3]);
                *(uint32_t*)((__half*)C + (size_t)r * N + c) = *(uint32_t*)&v0;
                *(uint32_t*)((__half*)C + (size_t)(r + 8) * N + c) = *(uint32_t*)&v1;
            }
        }
    }
}

// ---------------------------------------------------------------------------
// RoPE + scatter q,k (fp16 qkv in) -> fp16 [bh][t][d].
// ---------------------------------------------------------------------------
__global__ __launch_bounds__(256) void rope_scatter(
    const float* __restrict__ cosp, const float* __restrict__ sinp)
{
    int idx = blockIdx.x * blockDim.x + threadIdx.x;
    if (idx >= BB * TT * HH * 32) return;
    int d = idx & 31;
    int h = (idx >> 5) & (HH - 1);
    int t = (idx >> 9) & (TT - 1);
    int b = idx >> 20;

    const __half* row = g_qkvh + (size_t)(b * TT + t) * NQKV;
    int base = h * DD + d;

    float c0 = cosp[t * DD + d],      c1 = cosp[t * DD + d + 32];
    float s0 = sinp[t * DD + d],      s1 = sinp[t * DD + d + 32];

    float q0 = __half2float(row[base]),      q1 = __half2float(row[base + 32]);
    float k0 = __half2float(row[CC + base]), k1 = __half2float(row[CC + base + 32]);

    size_t hoff = ((size_t)(b * HH + h) * TT + t) * DD + d;
    g_qh[hoff]      = __float2half(q0 * c0 - q1 * s0);
    g_qh[hoff + 32] = __float2half(q1 * c1 + q0 * s1);
    g_kh[hoff]      = __float2half(k0 * c0 - k1 * s0);
    g_kh[hoff + 32] = __float2half(k1 * c1 + k0 * s1);
}

// ---------------------------------------------------------------------------
// V transpose: fp16 qkv v-part [b,t,h*64+d] -> g_vh [bh][d][t].
// ---------------------------------------------------------------------------
__global__ __launch_bounds__(256) void v_transpose()
{
    __shared__ __half s[64][40];

    const int bh = blockIdx.y;
    const int b = bh >> 4, h = bh & 15;
    const int t0 = blockIdx.x * 32;
    const int tid = threadIdx.x;

    {
        int t = tid >> 3;
        int d8 = (tid & 7) << 3;
        const __half* src = g_qkvh + (size_t)(b * TT + t0 + t) * NQKV + 2 * CC + h * DD + d8;
        uint4 v = *(const uint4*)src;
        __half hv[8];
        *(uint4*)hv = v;
        #pragma unroll
        for (int i = 0; i < 8; i++) s[d8 + i][t] = hv[i];
    }
    __syncthreads();

    {
        int d = tid >> 2;
        int tq = (tid & 3) << 3;
        uint4 v = *(const uint4*)&s[d][tq];
        __half* dst = g_vh + ((size_t)bh * DD + d) * TT + t0 + tq;
        *(uint4*)dst = v;
    }
}

// ---------------------------------------------------------------------------
// TMA fp16 causal flash attention; 3-stage pipeline; full-64-key softmax.
// K tile: [64 keys][128B d, SW128]; V tile: [64 d][128B t, SW128].
// ---------------------------------------------------------------------------
#define AKT_B 8192
#define ASTG (2*AKT_B)                      // K+V = 16384
#define AST 3
#define ATTN_SMEM (1024 + AST*ASTG)         // 50176

__global__ __launch_bounds__(256, 2) void attn_tma(
    const __grid_constant__ CUtensorMap mK,
    const __grid_constant__ CUtensorMap mV,
    float kscale)
{
    const int bh = blockIdx.y;
    const int q0 = (gridDim.x - 1 - blockIdx.x) * 128;
    const int b = bh >> 4, h = bh & 15;
    const int tid = threadIdx.x;
    const int lane = tid & 31;
    const int w = tid >> 5;
    const int gm = lane >> 2;
    const int gk = lane & 3;

    const __half* Qp = g_qh + (size_t)bh * TT * DD;

    extern __shared__ __align__(128) char smc[];
    uint32_t sb = (uint32_t)__cvta_generic_to_shared(smc);
    const uint32_t mbar = sb;
    char* tiles = smc + 1024;

    const int rowA = q0 + w * 16 + gm;
    const int wrow_lo = q0 + w * 16;
    const int wrow_hi = wrow_lo + 15;

    const int ntiles = (q0 + 128) / 64;

    if (tid == 0) {
        #pragma unroll
        for (int s = 0; s < AST; s++) mbar_init(mbar + 8 * s, 1);
    }
    __syncthreads();

    const uint32_t tiles_u32 = sb + 1024;
    auto prod = [&](int jt, int s) {
        uint32_t bar = mbar + 8 * s;
        mbar_expect_tx(bar, ASTG);
        tma3d(tiles_u32 + s * ASTG,         &mK, 0, jt * 64, bh, bar);
        tma3d(tiles_u32 + s * ASTG + AKT_B, &mV, jt * 64, 0, bh, bar);
    };
    if (tid == 0) {
        prod(0, 0);
        prod(1, 1);
        if (ntiles > 2) prod(2, 2);
    }

    uint32_t qf[4][4];
    #pragma unroll
    for (int s = 0; s < 4; s++) {
        const __half* r0 = Qp + (size_t)rowA * DD + 16 * s + 2 * gk;
        const __half* r1 = Qp + (size_t)(rowA + 8) * DD + 16 * s + 2 * gk;
        qf[s][0] = *(const uint32_t*)r0;
        qf[s][1] = *(const uint32_t*)r1;
        qf[s][2] = *(const uint32_t*)(r0 + 8);
        qf[s][3] = *(const uint32_t*)(r1 + 8);
    }

    float o[8][4];
    #pragma unroll
    for (int n = 0; n < 8; n++)
        #pragma unroll
        for (int r = 0; r < 4; r++) o[n][r] = 0.f;
    float mA = -1e30f, mB = -1e30f, lA = 0.f, lB = 0.f;

    for (int jt = 0; jt < ntiles; jt++) {
        const int st = jt % AST;
        mbar_wait(mbar + 8 * st, (uint32_t)((jt / AST) & 1));

        const char* Ks = tiles + st * ASTG;
        const char* Vs = Ks + AKT_B;
        const int j0 = jt * 64;

        if (j0 <= wrow_hi) {
            // ---- S = Q K^T (16 x 64), swizzled scalar B loads ----
            float sf[8][4];
            #pragma unroll
            for (int j = 0; j < 8; j++) {
                #pragma unroll
                for (int r = 0; r < 4; r++) sf[j][r] = 0.f;
                const char* kr = Ks + (8 * j + gm) * 128 + 4 * gk;
                #pragma unroll
                for (int s = 0; s < 4; s++) {
                    uint32_t bq[2];
                    bq[0] = *(const uint32_t*)(kr + (((2 * s)     ^ gm) << 4));
                    bq[1] = *(const uint32_t*)(kr + (((2 * s + 1) ^ gm) << 4));
                    mma_f16(sf[j], qf[s], bq);
                }
            }

            const bool needmask = (j0 + 63 > wrow_lo);
            float mxA = -1e30f, mxB = -1e30f;
            #pragma unroll
            for (int j = 0; j < 8; j++) {
                #pragma unroll
                for (int e = 0; e < 2; e++) {
                    int col = j0 + 8 * j + 2 * gk + e;
                    float v0 = sf[j][e] * kscale;
                    float v1 = sf[j][2 + e] * kscale;
                    if (needmask) {
                        if (col > rowA)     v0 = -1e30f;
                        if (col > rowA + 8) v1 = -1e30f;
                    }
                    sf[j][e] = v0; sf[j][2 + e] = v1;
                    mxA = fmaxf(mxA, v0); mxB = fmaxf(mxB, v1);
                }
            }
            mxA = fmaxf(mxA, __shfl_xor_sync(0xffffffffu, mxA, 1));
            mxA = fmaxf(mxA, __shfl_xor_sync(0xffffffffu, mxA, 2));
            mxB = fmaxf(mxB, __shfl_xor_sync(0xffffffffu, mxB, 1));
            mxB = fmaxf(mxB, __shfl_xor_sync(0xffffffffu, mxB, 2));

            float nmA = fmaxf(mA, mxA), nmB = fmaxf(mB, mxB);
            float aA = ex2(mA - nmA), aB = ex2(mB - nmB);
            mA = nmA; mB = nmB;

            #pragma unroll
            for (int n = 0; n < 8; n++) {
                o[n][0] *= aA; o[n][1] *= aA;
                o[n][2] *= aB; o[n][3] *= aB;
            }
            lA *= aA; lB *= aB;

            uint32_t phl[8][2];
            float slA = 0.f, slB = 0.f;
            #pragma unroll
            for (int j = 0; j < 8; j++) {
                float p0 = ex2(sf[j][0] - mA);
                float p1 = ex2(sf[j][1] - mA);
                float p2 = ex2(sf[j][2] - mB);
                float p3 = ex2(sf[j][3] - mB);
                slA += p0 + p1; slB += p2 + p3;
                __half2 h01 = __floats2half2_rn(p0, p1);
                __half2 h23 = __floats2half2_rn(p2, p3);
                phl[j][0] = *(const uint32_t*)&h01;
                phl[j][1] = *(const uint32_t*)&h23;
            }
            slA += __shfl_xor_sync(0xffffffffu, slA, 1);
            slA += __shfl_xor_sync(0xffffffffu, slA, 2);
            slB += __shfl_xor_sync(0xffffffffu, slB, 1);
            slB += __shfl_xor_sync(0xffffffffu, slB, 2);
            lA += slA; lB += slB;

            // ---- O += P V, swizzled scalar B loads from d-major V ----
            #pragma unroll
            for (int s2 = 0; s2 < 4; s2++) {
                uint32_t af[4] = { phl[2 * s2][0], phl[2 * s2][1],
                                   phl[2 * s2 + 1][0], phl[2 * s2 + 1][1] };
                const int gran = 2 * s2;
                #pragma unroll
                for (int n = 0; n < 8; n++) {
                    const char* vb = Vs + (8 * n + gm) * 128 + 4 * gk;
                    uint32_t bv[2];
                    bv[0] = *(const uint32_t*)(vb + (((gran)     ^ gm) << 4));
                    bv[1] = *(const uint32_t*)(vb + (((gran + 1) ^ gm) << 4));
                    mma_f16(o[n], af, bv);
                }
            }
        }
        __syncthreads();
        if (tid == 0 && jt + AST < ntiles) prod(jt + AST, st);
    }

    float invA = 1.f / lA, invB = 1.f / lB;
    __half* dstA = g_atth + (size_t)(b * TT + rowA) * CC + h * DD;
    __half* dstB = g_atth + (size_t)(b * TT + rowA + 8) * CC + h * DD;
    #pragma unroll
    for (int n = 0; n < 8; n++) {
        int cix = 8 * n + 2 * gk;
        __half2 v0 = __floats2half2_rn(o[n][0] * invA, o[n][1] * invA);
        __half2 v1 = __floats2half2_rn(o[n][2] * invB, o[n][3] * invB);
        *(uint32_t*)(dstA + cix) = *(uint32_t*)&v0;
        *(uint32_t*)(dstB + cix) = *(uint32_t*)&v1;
    }
}

// ---------------------------------------------------------------------------
// Host: tensor-map encode via driver entry point
// ---------------------------------------------------------------------------
typedef CUresult (*PFN_tmap_encode)(
    CUtensorMap*, CUtensorMapDataType, cuuint32_t, void*,
    const cuuint64_t*, const cuuint64_t*, const cuuint32_t*, const cuuint32_t*,
    CUtensorMapInterleave, CUtensorMapSwizzle, CUtensorMapL2promotion,
    CUtensorMapFloatOOBfill);

static PFN_tmap_encode get_encoder() {
    void* fn = nullptr;
    cudaDriverEntryPointQueryResult qr;
    cudaGetDriverEntryPoint("cuTensorMapEncodeTiled", &fn, cudaEnableDefault, &qr);
    return (PFN_tmap_encode)fn;
}

static void enc2d(PFN_tmap_encode f, CUtensorMap* m, void* base,
                  uint64_t d0, uint64_t d1, uint32_t b0, uint32_t b1) {
    cuuint64_t dims[2] = {d0, d1};
    cuuint64_t str[1]  = {d0 * 2};
    cuuint32_t box[2]  = {b0, b1};
    cuuint32_t es[2]   = {1, 1};
    f(m, CU_TENSOR_MAP_DATA_TYPE_FLOAT16, 2, base, dims, str, box, es,
      CU_TENSOR_MAP_INTERLEAVE_NONE, CU_TENSOR_MAP_SWIZZLE_128B,
      CU_TENSOR_MAP_L2_PROMOTION_L2_128B, CU_TENSOR_MAP_FLOAT_OOB_FILL_NONE);
}

static void enc3d(PFN_tmap_encode f, CUtensorMap* m, void* base,
                  uint64_t d0, uint64_t d1, uint64_t d2,
                  uint32_t b0, uint32_t b1) {
    cuuint64_t dims[3] = {d0, d1, d2};
    cuuint64_t str[2]  = {d0 * 2, d0 * d1 * 2};
    cuuint32_t box[3]  = {b0, b1, 1};
    cuuint32_t es[3]   = {1, 1, 1};
    f(m, CU_TENSOR_MAP_DATA_TYPE_FLOAT16, 3, base, dims, str, box, es,
      CU_TENSOR_MAP_INTERLEAVE_NONE, CU_TENSOR_MAP_SWIZZLE_128B,
      CU_TENSOR_MAP_L2_PROMOTION_L2_128B, CU_TENSOR_MAP_FLOAT_OOB_FILL_NONE);
}

// ---------------------------------------------------------------------------
// Launch
// ---------------------------------------------------------------------------
extern "C" void kernel_launch(void* const* d_in, const int* in_sizes, int n_in,
                              void* d_out, int out_size)
{
    const float* x     = (const float*)d_in[0];
    const float* cosp  = (const float*)d_in[1];
    const float* sinp  = (const float*)d_in[2];
    const float* w_qkv = (const float*)d_in[3];
    const float* w_out = (const float*)d_in[4];
    float* out = (float*)d_out;

    __half *p_qkvh, *p_xh, *p_wqkvh, *p_wouth, *p_kh, *p_vh, *p_atth;
    cudaGetSymbolAddress((void**)&p_qkvh,  g_qkvh);
    cudaGetSymbolAddress((void**)&p_xh,    g_xh);
    cudaGetSymbolAddress((void**)&p_wqkvh, g_wqkvh);
    cudaGetSymbolAddress((void**)&p_wouth, g_wouth);
    cudaGetSymbolAddress((void**)&p_kh,    g_kh);
    cudaGetSymbolAddress((void**)&p_vh,    g_vh);
    cudaGetSymbolAddress((void**)&p_atth,  g_atth);

    PFN_tmap_encode enc = get_encoder();

    CUtensorMap mX, mWqkv, mAtt, mWout, mK, mV;
    enc2d(enc, &mX,    p_xh,    CC, MM,   64, 128);
    enc2d(enc, &mWqkv, p_wqkvh, CC, NQKV, 64, 128);
    enc2d(enc, &mAtt,  p_atth,  CC, MM,   64, 128);
    enc2d(enc, &mWout, p_wouth, CC, CC,   64, 128);
    enc3d(enc, &mK, p_kh, DD, TT, BB * HH, 64, 64);
    enc3d(enc, &mV, p_vh, TT, DD, BB * HH, 64, 64);

    cudaFuncSetAttribute(gemm_tma<__half>,
                         cudaFuncAttributeMaxDynamicSharedMemorySize, GEMM_SMEM);
    cudaFuncSetAttribute(gemm_tma<float>,
                         cudaFuncAttributeMaxDynamicSharedMemorySize, GEMM_SMEM);
    cudaFuncSetAttribute(attn_tma,
                         cudaFuncAttributeMaxDynamicSharedMemorySize, ATTN_SMEM);

    // 0) fp32 -> fp16 converts
    cvt_h<<<(MM * CC) / (8 * 256), 256>>>(x, p_xh, MM * CC);
    cvt_h<<<(NQKV * CC) / (8 * 256), 256>>>(w_qkv, p_wqkvh, NQKV * CC);
    cvt_h<<<(CC * CC) / (8 * 256), 256>>>(w_out, p_wouth, CC * CC);

    // 1) qkv = x @ w_qkv^T (fp16 out)
    {
        dim3 grid(NQKV / 128, MM / 128);
        gemm_tma<__half><<<grid, 256, GEMM_SMEM>>>(mX, mWqkv, p_qkvh, NQKV, CC);
    }

    // 2a) RoPE q,k -> fp16 [bh][t][d]
    {
        int total = BB * TT * HH * 32;
        rope_scatter<<<(total + 255) / 256, 256>>>(cosp, sinp);
    }
    // 2b) V -> fp16 [bh][d][t]
    {
        dim3 grid(TT / 32, BB * HH);
        v_transpose<<<grid, 256>>>();
    }

    // 3) TMA fp16 causal flash attention
    {
        dim3 grid(TT / 128, BB * HH);
        attn_tma<<<grid, 256, ATTN_SMEM>>>(mK, mV, 0.125f * 1.44269504f);
    }

    // 4) out = att @ w_out^T (fp32 out)
    {
        dim3 grid(CC / 128, MM / 128);
        gemm_tma<float><<<grid, 256, GEMM_SMEM>>>(mAtt, mWout, out, CC, CC);
    }
}

// round 12
// speedup vs baseline: 1.8298x; 1.0486x over previous
#include <cuda_runtime.h>
#include <cuda.h>
#include <cuda_fp16.h>
#include <cstdint>

// Problem constants
#define BB 2
#define TT 2048
#define HH 16
#define DD 64
#define CC 1024
#define MM (BB*TT)        // 4096 rows
#define NQKV (3*CC)       // 3072

// Scratch (device globals -- no allocation allowed)
__device__ __half g_qkvh[MM * NQKV];       // [4096, 3072] fp16 qkv
__device__ __half g_xh[MM * CC];           // x in fp16
__device__ __half g_wqkvh[NQKV * CC];      // w_qkv in fp16
__device__ __half g_wouth[CC * CC];        // w_out in fp16
__device__ __half g_qh[BB*HH*TT*DD];       // [bh][t][d] fp16
__device__ __half g_kh[BB*HH*TT*DD];       // [bh][t][d] fp16
__device__ __half g_vh[BB*HH*DD*TT];       // [bh][d][t] fp16 (d-major)
__device__ __half g_atth[MM * CC];         // attention out, fp16 [B,T,C]

__device__ __forceinline__ float ex2(float x) {
    float y;
    asm("ex2.approx.ftz.f32 %0, %1;" : "=f"(y) : "f"(x));
    return y;
}

__device__ __forceinline__ void mma_f16(float* d, const uint32_t* a, const uint32_t* b) {
    asm volatile(
        "mma.sync.aligned.m16n8k16.row.col.f32.f16.f16.f32 "
        "{%0,%1,%2,%3},{%4,%5,%6,%7},{%8,%9},{%0,%1,%2,%3};\n"
        : "+f"(d[0]), "+f"(d[1]), "+f"(d[2]), "+f"(d[3])
        : "r"(a[0]), "r"(a[1]), "r"(a[2]), "r"(a[3]), "r"(b[0]), "r"(b[1]));
}

__device__ __forceinline__ void ldsm4(uint32_t* r, uint32_t addr) {
    asm volatile("ldmatrix.sync.aligned.m8n8.x4.shared.b16 {%0,%1,%2,%3}, [%4];"
                 : "=r"(r[0]), "=r"(r[1]), "=r"(r[2]), "=r"(r[3]) : "r"(addr));
}

__device__ __forceinline__ void mbar_init(uint32_t addr, uint32_t cnt) {
    asm volatile("mbarrier.init.shared.b64 [%0], %1;" :: "r"(addr), "r"(cnt) : "memory");
}
__device__ __forceinline__ void mbar_expect_tx(uint32_t addr, uint32_t bytes) {
    asm volatile("mbarrier.arrive.expect_tx.shared.b64 _, [%0], %1;"
                 :: "r"(addr), "r"(bytes) : "memory");
}
__device__ __forceinline__ void mbar_wait(uint32_t addr, uint32_t parity) {
    asm volatile(
        "{\n\t.reg .pred P;\n"
        "W:\n\tmbarrier.try_wait.parity.acquire.cta.shared::cta.b64 P, [%0], %1, 0x989680;\n"
        "\t@P bra D;\n\tbra W;\nD:\n\t}"
        :: "r"(addr), "r"(parity) : "memory");
}
__device__ __forceinline__ void tma2d(uint32_t smem, const CUtensorMap* map,
                                      int x, int y, uint32_t bar) {
    asm volatile(
        "cp.async.bulk.tensor.2d.shared::cta.global.tile.mbarrier::complete_tx::bytes "
        "[%0], [%1, {%2, %3}], [%4];"
        :: "r"(smem), "l"(map), "r"(x), "r"(y), "r"(bar) : "memory");
}
__device__ __forceinline__ void tma3d(uint32_t smem, const CUtensorMap* map,
                                      int x, int y, int z, uint32_t bar) {
    asm volatile(
        "cp.async.bulk.tensor.3d.shared::cta.global.tile.mbarrier::complete_tx::bytes "
        "[%0], [%1, {%2, %3, %4}], [%5];"
        :: "r"(smem), "l"(map), "r"(x), "r"(y), "r"(z), "r"(bar) : "memory");
}

// ---------------------------------------------------------------------------
// fp32 -> fp16 convert (vectorized, 8 elems/thread)
// ---------------------------------------------------------------------------
__global__ __launch_bounds__(256) void cvt_h(
    const float* __restrict__ src, __half* __restrict__ dst, int n)
{
    int i = (blockIdx.x * blockDim.x + threadIdx.x) * 8;
    if (i >= n) return;
    float4 v0 = *(const float4*)(src + i);
    float4 v1 = *(const float4*)(src + i + 4);
    __half2 h0 = __floats2half2_rn(v0.x, v0.y);
    __half2 h1 = __floats2half2_rn(v0.z, v0.w);
    __half2 h2 = __floats2half2_rn(v1.x, v1.y);
    __half2 h3 = __floats2half2_rn(v1.z, v1.w);
    uint4 o;
    o.x = *(uint32_t*)&h0; o.y = *(uint32_t*)&h1;
    o.z = *(uint32_t*)&h2; o.w = *(uint32_t*)&h3;
    *(uint4*)(dst + i) = o;
}

// ---------------------------------------------------------------------------
// TMA fp16 GEMM: C[m][n] = sum_k A[m][k]*B[n][k]; OutT = float or __half.
// Block 128x128, BK=64, 256 thr (8 warps, 64x32 each), 3-stage TMA+mbarrier.
// SW128 swizzled tiles (128B rows): granule ^= row&7.
// ---------------------------------------------------------------------------
#define GS 3
#define GA_B 16384
#define GSTG (2*GA_B)                       // 32768 per stage (A+B)
#define GEMM_SMEM (1024 + GS*GSTG)          // 99328

template <typename OutT>
__global__ __launch_bounds__(256, 2) void gemm_tma(
    const __grid_constant__ CUtensorMap mA,
    const __grid_constant__ CUtensorMap mB,
    OutT* __restrict__ C, int N, int K)
{
    extern __shared__ __align__(128) char smc[];
    uint32_t sb = (uint32_t)__cvta_generic_to_shared(smc);
    const uint32_t mbar = sb;
    const uint32_t tiles = sb + 1024;

    const int tid  = threadIdx.x;
    const int lane = tid & 31;
    const int warp = tid >> 5;
    const int wm = warp & 1;
    const int wn = warp >> 1;
    const int m0 = blockIdx.y * 128;
    const int n0 = blockIdx.x * 128;
    const int g  = lane >> 3;
    const int lr = lane & 7;
    const int gm = lane >> 2;
    const int gk = lane & 3;

    const int NI = K / 64;

    if (tid == 0) {
        #pragma unroll
        for (int s = 0; s < GS; s++) mbar_init(mbar + 8 * s, 1);
    }
    __syncthreads();

    auto prod = [&](int kt, int s) {
        uint32_t bar = mbar + 8 * s;
        mbar_expect_tx(bar, GSTG);
        tma2d(tiles + s * GSTG,        &mA, kt * 64, m0, bar);
        tma2d(tiles + s * GSTG + GA_B, &mB, kt * 64, n0, bar);
    };
    if (tid == 0) { prod(0, 0); prod(1, 1); prod(2, 2); }

    uint32_t arow[4], brow[2];
    #pragma unroll
    for (int i = 0; i < 4; i++)
        arow[i] = (uint32_t)((wm * 64 + 16 * i + (g & 1) * 8 + lr) * 128);
    #pragma unroll
    for (int jj = 0; jj < 2; jj++)
        brow[jj] = (uint32_t)(GA_B + (wn * 32 + 16 * jj + (g >> 1) * 8 + lr) * 128);

    float acc[16][4];
    #pragma unroll
    for (int t = 0; t < 16; t++)
        #pragma unroll
        for (int r = 0; r < 4; r++) acc[t][r] = 0.f;

    for (int it = 0; it < NI; it++) {
        const int s = it % GS;
        const uint32_t ph = (uint32_t)((it / GS) & 1);
        mbar_wait(mbar + 8 * s, ph);

        const uint32_t stg = tiles + s * GSTG;
        #pragma unroll
        for (int ks = 0; ks < 4; ks++) {
            uint32_t af[4][4];
            const uint32_t ag = (uint32_t)(((2 * ks + (g >> 1)) ^ lr) << 4);
            #pragma unroll
            for (int i = 0; i < 4; i++)
                ldsm4(af[i], stg + arow[i] + ag);
            uint32_t bf[2][4];
            const uint32_t bg = (uint32_t)(((2 * ks + (g & 1)) ^ lr) << 4);
            #pragma unroll
            for (int jj = 0; jj < 2; jj++)
                ldsm4(bf[jj], stg + brow[jj] + bg);

            #pragma unroll
            for (int i = 0; i < 4; i++)
                #pragma unroll
                for (int jj = 0; jj < 2; jj++) {
                    mma_f16(acc[i * 4 + 2 * jj],     af[i], &bf[jj][0]);
                    mma_f16(acc[i * 4 + 2 * jj + 1], af[i], &bf[jj][2]);
                }
        }
        __syncthreads();
        if (tid == 0 && it + GS < NI) prod(it + GS, s);
    }

    #pragma unroll
    for (int i = 0; i < 4; i++) {
        #pragma unroll
        for (int nn = 0; nn < 4; nn++) {
            float* a = acc[i * 4 + nn];
            int r = m0 + wm * 64 + 16 * i + gm;
            int c = n0 + wn * 32 + 8 * nn + (gk << 1);
            if constexpr (sizeof(OutT) == 4) {
                float2 v0 = {a[0], a[1]};
                float2 v1 = {a[2], a[3]};
                *(float2*)((float*)C + (size_t)r * N + c) = v0;
                *(float2*)((float*)C + (size_t)(r + 8) * N + c) = v1;
            } else {
                __half2 v0 = __floats2half2_rn(a[0], a[1]);
                __half2 v1 = __floats2half2_rn(a[2], a[3]);
                *(uint32_t*)((__half*)C + (size_t)r * N + c) = *(uint32_t*)&v0;
                *(uint32_t*)((__half*)C + (size_t)(r + 8) * N + c) = *(uint32_t*)&v1;
            }
        }
    }
}

// ---------------------------------------------------------------------------
// RoPE + scatter q,k (fp16 qkv in) -> fp16 [bh][t][d].
// ---------------------------------------------------------------------------
__global__ __launch_bounds__(256) void rope_scatter(
    const float* __restrict__ cosp, const float* __restrict__ sinp)
{
    int idx = blockIdx.x * blockDim.x + threadIdx.x;
    if (idx >= BB * TT * HH * 32) return;
    int d = idx & 31;
    int h = (idx >> 5) & (HH - 1);
    int t = (idx >> 9) & (TT - 1);
    int b = idx >> 20;

    const __half* row = g_qkvh + (size_t)(b * TT + t) * NQKV;
    int base = h * DD + d;

    float c0 = cosp[t * DD + d],      c1 = cosp[t * DD + d + 32];
    float s0 = sinp[t * DD + d],      s1 = sinp[t * DD + d + 32];

    float q0 = __half2float(row[base]),      q1 = __half2float(row[base + 32]);
    float k0 = __half2float(row[CC + base]), k1 = __half2float(row[CC + base + 32]);

    size_t hoff = ((size_t)(b * HH + h) * TT + t) * DD + d;
    g_qh[hoff]      = __float2half(q0 * c0 - q1 * s0);
    g_qh[hoff + 32] = __float2half(q1 * c1 + q0 * s1);
    g_kh[hoff]      = __float2half(k0 * c0 - k1 * s0);
    g_kh[hoff + 32] = __float2half(k1 * c1 + k0 * s1);
}

// ---------------------------------------------------------------------------
// V transpose: fp16 qkv v-part [b,t,h*64+d] -> g_vh [bh][d][t].
// ---------------------------------------------------------------------------
__global__ __launch_bounds__(256) void v_transpose()
{
    __shared__ __half s[64][40];

    const int bh = blockIdx.y;
    const int b = bh >> 4, h = bh & 15;
    const int t0 = blockIdx.x * 32;
    const int tid = threadIdx.x;

    {
        int t = tid >> 3;
        int d8 = (tid & 7) << 3;
        const __half* src = g_qkvh + (size_t)(b * TT + t0 + t) * NQKV + 2 * CC + h * DD + d8;
        uint4 v = *(const uint4*)src;
        __half hv[8];
        *(uint4*)hv = v;
        #pragma unroll
        for (int i = 0; i < 8; i++) s[d8 + i][t] = hv[i];
    }
    __syncthreads();

    {
        int d = tid >> 2;
        int tq = (tid & 3) << 3;
        uint4 v = *(const uint4*)&s[d][tq];
        __half* dst = g_vh + ((size_t)bh * DD + d) * TT + t0 + tq;
        *(uint4*)dst = v;
    }
}

// ---------------------------------------------------------------------------
// TMA fp16 causal flash attention; B-fragments via ldmatrix.x4 (4x fewer
// LSU ops than scalar LDS -- LSU was co-saturating with the tensor pipe).
// K tile: [64 keys][128B d, SW128]; V tile: [64 d][128B t, SW128].
// ---------------------------------------------------------------------------
#define AKT_B 8192
#define ASTG (2*AKT_B)                      // K+V = 16384
#define AST 3
#define ATTN_SMEM (1024 + AST*ASTG)         // 50176

__global__ __launch_bounds__(256, 2) void attn_tma(
    const __grid_constant__ CUtensorMap mK,
    const __grid_constant__ CUtensorMap mV,
    float kscale)
{
    const int bh = blockIdx.y;
    const int q0 = (gridDim.x - 1 - blockIdx.x) * 128;
    const int b = bh >> 4, h = bh & 15;
    const int tid = threadIdx.x;
    const int lane = tid & 31;
    const int w = tid >> 5;
    const int gm = lane >> 2;
    const int gk = lane & 3;
    const int g  = lane >> 3;
    const int lr = lane & 7;

    const __half* Qp = g_qh + (size_t)bh * TT * DD;

    extern __shared__ __align__(128) char smc[];
    uint32_t sb = (uint32_t)__cvta_generic_to_shared(smc);
    const uint32_t mbar = sb;

    const int rowA = q0 + w * 16 + gm;
    const int wrow_lo = q0 + w * 16;
    const int wrow_hi = wrow_lo + 15;

    const int ntiles = (q0 + 128) / 64;

    if (tid == 0) {
        #pragma unroll
        for (int s = 0; s < AST; s++) mbar_init(mbar + 8 * s, 1);
    }
    __syncthreads();

    const uint32_t tiles_u32 = sb + 1024;
    auto prod = [&](int jt, int s) {
        uint32_t bar = mbar + 8 * s;
        mbar_expect_tx(bar, ASTG);
        tma3d(tiles_u32 + s * ASTG,         &mK, 0, jt * 64, bh, bar);
        tma3d(tiles_u32 + s * ASTG + AKT_B, &mV, jt * 64, 0, bh, bar);
    };
    if (tid == 0) {
        prod(0, 0);
        prod(1, 1);
        if (ntiles > 2) prod(2, 2);
    }

    uint32_t qf[4][4];
    #pragma unroll
    for (int s = 0; s < 4; s++) {
        const __half* r0 = Qp + (size_t)rowA * DD + 16 * s + 2 * gk;
        const __half* r1 = Qp + (size_t)(rowA + 8) * DD + 16 * s + 2 * gk;
        qf[s][0] = *(const uint32_t*)r0;
        qf[s][1] = *(const uint32_t*)r1;
        qf[s][2] = *(const uint32_t*)(r0 + 8);
        qf[s][3] = *(const uint32_t*)(r1 + 8);
    }

    // ldmatrix per-lane row base within a 64x128B tile: row = 16*jp + (g>>1)*8 + lr
    const uint32_t lrowoff = (uint32_t)(((g >> 1) * 8 + lr) * 128);

    float o[8][4];
    #pragma unroll
    for (int n = 0; n < 8; n++)
        #pragma unroll
        for (int r = 0; r < 4; r++) o[n][r] = 0.f;
    float mA = -1e30f, mB = -1e30f, lA = 0.f, lB = 0.f;

    for (int jt = 0; jt < ntiles; jt++) {
        const int st = jt % AST;
        mbar_wait(mbar + 8 * st, (uint32_t)((jt / AST) & 1));

        const uint32_t Ks = tiles_u32 + st * ASTG;
        const uint32_t Vs = Ks + AKT_B;
        const int j0 = jt * 64;

        if (j0 <= wrow_hi) {
            // ---- S = Q K^T (16 x 64): ldmatrix.x4 B-frags ----
            float sf[8][4];
            #pragma unroll
            for (int j = 0; j < 8; j++)
                #pragma unroll
                for (int r = 0; r < 4; r++) sf[j][r] = 0.f;
            #pragma unroll
            for (int s = 0; s < 4; s++) {
                const uint32_t bg = (uint32_t)(((2 * s + (g & 1)) ^ lr) << 4);
                #pragma unroll
                for (int jp = 0; jp < 4; jp++) {
                    uint32_t bf[4];
                    ldsm4(bf, Ks + (uint32_t)(16 * jp * 128) + lrowoff + bg);
                    mma_f16(sf[2 * jp],     qf[s], &bf[0]);
                    mma_f16(sf[2 * jp + 1], qf[s], &bf[2]);
                }
            }

            const bool needmask = (j0 + 63 > wrow_lo);
            float mxA = -1e30f, mxB = -1e30f;
            #pragma unroll
            for (int j = 0; j < 8; j++) {
                #pragma unroll
                for (int e = 0; e < 2; e++) {
                    int col = j0 + 8 * j + 2 * gk + e;
                    float v0 = sf[j][e] * kscale;
                    float v1 = sf[j][2 + e] * kscale;
                    if (needmask) {
                        if (col > rowA)     v0 = -1e30f;
                        if (col > rowA + 8) v1 = -1e30f;
                    }
                    sf[j][e] = v0; sf[j][2 + e] = v1;
                    mxA = fmaxf(mxA, v0); mxB = fmaxf(mxB, v1);
                }
            }
            mxA = fmaxf(mxA, __shfl_xor_sync(0xffffffffu, mxA, 1));
            mxA = fmaxf(mxA, __shfl_xor_sync(0xffffffffu, mxA, 2));
            mxB = fmaxf(mxB, __shfl_xor_sync(0xffffffffu, mxB, 1));
            mxB = fmaxf(mxB, __shfl_xor_sync(0xffffffffu, mxB, 2));

            float nmA = fmaxf(mA, mxA), nmB = fmaxf(mB, mxB);
            float aA = ex2(mA - nmA), aB = ex2(mB - nmB);
            mA = nmA; mB = nmB;

            #pragma unroll
            for (int n = 0; n < 8; n++) {
                o[n][0] *= aA; o[n][1] *= aA;
                o[n][2] *= aB; o[n][3] *= aB;
            }
            lA *= aA; lB *= aB;

            uint32_t phl[8][2];
            float slA = 0.f, slB = 0.f;
            #pragma unroll
            for (int j = 0; j < 8; j++) {
                float p0 = ex2(sf[j][0] - mA);
                float p1 = ex2(sf[j][1] - mA);
                float p2 = ex2(sf[j][2] - mB);
                float p3 = ex2(sf[j][3] - mB);
                slA += p0 + p1; slB += p2 + p3;
                __half2 h01 = __floats2half2_rn(p0, p1);
                __half2 h23 = __floats2half2_rn(p2, p3);
                phl[j][0] = *(const uint32_t*)&h01;
                phl[j][1] = *(const uint32_t*)&h23;
            }
            slA += __shfl_xor_sync(0xffffffffu, slA, 1);
            slA += __shfl_xor_sync(0xffffffffu, slA, 2);
            slB += __shfl_xor_sync(0xffffffffu, slB, 1);
            slB += __shfl_xor_sync(0xffffffffu, slB, 2);
            lA += slA; lB += slB;

            // ---- O += P V: ldmatrix.x4 B-frags from d-major V ----
            #pragma unroll
            for (int s2 = 0; s2 < 4; s2++) {
                uint32_t af[4] = { phl[2 * s2][0], phl[2 * s2][1],
                                   phl[2 * s2 + 1][0], phl[2 * s2 + 1][1] };
                const uint32_t vg = (uint32_t)(((2 * s2 + (g & 1)) ^ lr) << 4);
                #pragma unroll
                for (int jp = 0; jp < 4; jp++) {
                    uint32_t bf[4];
                    ldsm4(bf, Vs + (uint32_t)(16 * jp * 128) + lrowoff + vg);
                    mma_f16(o[2 * jp],     af, &bf[0]);
                    mma_f16(o[2 * jp + 1], af, &bf[2]);
                }
            }
        }
        __syncthreads();
        if (tid == 0 && jt + AST < ntiles) prod(jt + AST, st);
    }

    float invA = 1.f / lA, invB = 1.f / lB;
    __half* dstA = g_atth + (size_t)(b * TT + rowA) * CC + h * DD;
    __half* dstB = g_atth + (size_t)(b * TT + rowA + 8) * CC + h * DD;
    #pragma unroll
    for (int n = 0; n < 8; n++) {
        int cix = 8 * n + 2 * gk;
        __half2 v0 = __floats2half2_rn(o[n][0] * invA, o[n][1] * invA);
        __half2 v1 = __floats2half2_rn(o[n][2] * invB, o[n][3] * invB);
        *(uint32_t*)(dstA + cix) = *(uint32_t*)&v0;
        *(uint32_t*)(dstB + cix) = *(uint32_t*)&v1;
    }
}

// ---------------------------------------------------------------------------
// Host: tensor-map encode via driver entry point
// ---------------------------------------------------------------------------
typedef CUresult (*PFN_tmap_encode)(
    CUtensorMap*, CUtensorMapDataType, cuuint32_t, void*,
    const cuuint64_t*, const cuuint64_t*, const cuuint32_t*, const cuuint32_t*,
    CUtensorMapInterleave, CUtensorMapSwizzle, CUtensorMapL2promotion,
    CUtensorMapFloatOOBfill);

static PFN_tmap_encode get_encoder() {
    void* fn = nullptr;
    cudaDriverEntryPointQueryResult qr;
    cudaGetDriverEntryPoint("cuTensorMapEncodeTiled", &fn, cudaEnableDefault, &qr);
    return (PFN_tmap_encode)fn;
}

static void enc2d(PFN_tmap_encode f, CUtensorMap* m, void* base,
                  uint64_t d0, uint64_t d1, uint32_t b0, uint32_t b1) {
    cuuint64_t dims[2] = {d0, d1};
    cuuint64_t str[1]  = {d0 * 2};
    cuuint32_t box[2]  = {b0, b1};
    cuuint32_t es[2]   = {1, 1};
    f(m, CU_TENSOR_MAP_DATA_TYPE_FLOAT16, 2, base, dims, str, box, es,
      CU_TENSOR_MAP_INTERLEAVE_NONE, CU_TENSOR_MAP_SWIZZLE_128B,
      CU_TENSOR_MAP_L2_PROMOTION_L2_128B, CU_TENSOR_MAP_FLOAT_OOB_FILL_NONE);
}

static void enc3d(PFN_tmap_encode f, CUtensorMap* m, void* base,
                  uint64_t d0, uint64_t d1, uint64_t d2,
                  uint32_t b0, uint32_t b1) {
    cuuint64_t dims[3] = {d0, d1, d2};
    cuuint64_t str[2]  = {d0 * 2, d0 * d1 * 2};
    cuuint32_t box[3]  = {b0, b1, 1};
    cuuint32_t es[3]   = {1, 1, 1};
    f(m, CU_TENSOR_MAP_DATA_TYPE_FLOAT16, 3, base, dims, str, box, es,
      CU_TENSOR_MAP_INTERLEAVE_NONE, CU_TENSOR_MAP_SWIZZLE_128B,
      CU_TENSOR_MAP_L2_PROMOTION_L2_128B, CU_TENSOR_MAP_FLOAT_OOB_FILL_NONE);
}

// ---------------------------------------------------------------------------
// Launch
// ---------------------------------------------------------------------------
extern "C" void kernel_launch(void* const* d_in, const int* in_sizes, int n_in,
                              void* d_out, int out_size)
{
    const float* x     = (const float*)d_in[0];
    const float* cosp  = (const float*)d_in[1];
    const float* sinp  = (const float*)d_in[2];
    const float* w_qkv = (const float*)d_in[3];
    const float* w_out = (const float*)d_in[4];
    float* out = (float*)d_out;

    __half *p_qkvh, *p_xh, *p_wqkvh, *p_wouth, *p_kh, *p_vh, *p_atth;
    cudaGetSymbolAddress((void**)&p_qkvh,  g_qkvh);
    cudaGetSymbolAddress((void**)&p_xh,    g_xh);
    cudaGetSymbolAddress((void**)&p_wqkvh, g_wqkvh);
    cudaGetSymbolAddress((void**)&p_wouth, g_wouth);
    cudaGetSymbolAddress((void**)&p_kh,    g_kh);
    cudaGetSymbolAddress((void**)&p_vh,    g_vh);
    cudaGetSymbolAddress((void**)&p_atth,  g_atth);

    PFN_tmap_encode enc = get_encoder();

    CUtensorMap mX, mWqkv, mAtt, mWout, mK, mV;
    enc2d(enc, &mX,    p_xh,    CC, MM,   64, 128);
    enc2d(enc, &mWqkv, p_wqkvh, CC, NQKV, 64, 128);
    enc2d(enc, &mAtt,  p_atth,  CC, MM,   64, 128);
    enc2d(enc, &mWout, p_wouth, CC, CC,   64, 128);
    enc3d(enc, &mK, p_kh, DD, TT, BB * HH, 64, 64);
    enc3d(enc, &mV, p_vh, TT, DD, BB * HH, 64, 64);

    cudaFuncSetAttribute(gemm_tma<__half>,
                         cudaFuncAttributeMaxDynamicSharedMemorySize, GEMM_SMEM);
    cudaFuncSetAttribute(gemm_tma<float>,
                         cudaFuncAttributeMaxDynamicSharedMemorySize, GEMM_SMEM);
    cudaFuncSetAttribute(attn_tma,
                         cudaFuncAttributeMaxDynamicSharedMemorySize, ATTN_SMEM);

    // 0) fp32 -> fp16 converts
    cvt_h<<<(MM * CC) / (8 * 256), 256>>>(x, p_xh, MM * CC);
    cvt_h<<<(NQKV * CC) / (8 * 256), 256>>>(w_qkv, p_wqkvh, NQKV * CC);
    cvt_h<<<(CC * CC) / (8 * 256), 256>>>(w_out, p_wouth, CC * CC);

    // 1) qkv = x @ w_qkv^T (fp16 out)
    {
        dim3 grid(NQKV / 128, MM / 128);
        gemm_tma<__half><<<grid, 256, GEMM_SMEM>>>(mX, mWqkv, p_qkvh, NQKV, CC);
    }

    // 2a) RoPE q,k -> fp16 [bh][t][d]
    {
        int total = BB * TT * HH * 32;
        rope_scatter<<<(total + 255) / 256, 256>>>(cosp, sinp);
    }
    // 2b) V -> fp16 [bh][d][t]
    {
        dim3 grid(TT / 32, BB * HH);
        v_transpose<<<grid, 256>>>();
    }

    // 3) TMA fp16 causal flash attention (ldmatrix B-frags)
    {
        dim3 grid(TT / 128, BB * HH);
        attn_tma<<<grid, 256, ATTN_SMEM>>>(mK, mV, 0.125f * 1.44269504f);
    }

    // 4) out = att @ w_out^T (fp32 out)
    {
        dim3 grid(CC / 128, MM / 128);
        gemm_tma<float><<<grid, 256, GEMM_SMEM>>>(mAtt, mWout, out, CC, CC);
    }
}